// round 1
// baseline (speedup 1.0000x reference)
#include <cuda_runtime.h>
#include <cuda_bf16.h>
#include <cstdint>

// Problem constants (fixed by the dataset)
#define BB 4
#define LL 1024
#define HH 32
#define WW 32
#define CC 768
#define NN 16
#define DR 48
#define KK 4
#define MTOT (BB*LL)          // 4096
#define DBLC (DR + 2*NN)      // 80

// ---------------- scratch (no allocations allowed) ----------------
__device__ float g_xn   [MTOT*CC];
__device__ float g_xz   [MTOT*2*CC];
__device__ float g_uc   [MTOT*CC];
__device__ float g_dbl  [MTOT*DBLC];
__device__ float g_dt   [MTOT*CC];
__device__ float g_y    [MTOT*CC];
__device__ float g_fused[MTOT*2*CC];
__device__ float g_h    [MTOT*CC];
__device__ int   g_idx_cw [LL];
__device__ int   g_idx_ccw[LL];

// ---------------- spiral index generation (closed form per cell) ----------------
__global__ void spiral_idx_kernel(int* idx_cw, int* idx_ccw) {
    int cell = threadIdx.x;            // 1024 threads
    int i = cell / WW, j = cell % WW;
    int r = min(min(i, j), min(HH - 1 - i, WW - 1 - j));
    int h = HH - 2 * r, w = WW - 2 * r;
    int prior = HH * WW - h * w;
    // clockwise
    int pos;
    if (i == r)                pos = j - r;                                   // top L->R
    else if (j == WW - 1 - r)  pos = (w - 1) + (i - r);                       // right T->B
    else if (i == HH - 1 - r)  pos = (w - 1) + (h - 1) + (WW - 1 - r - j);    // bottom R->L
    else                       pos = 2*(w - 1) + (h - 1) + (HH - 1 - r - i);  // left B->T
    idx_cw[prior + pos] = cell;
    // counter-clockwise
    if (i == r)                pos = (WW - 1 - r) - j;                        // top R->L
    else if (j == r)           pos = (w - 1) + (i - r);                       // left T->B
    else if (i == HH - 1 - r)  pos = (w - 1) + (h - 1) + (j - r);             // bottom L->R
    else                       pos = 2*(w - 1) + (h - 1) + (HH - 1 - r - i);  // right B->T
    idx_ccw[prior + pos] = cell;
}

// ---------------- layernorm ----------------
__global__ void layernorm_kernel(const float* __restrict__ x,
                                 const float* __restrict__ w,
                                 const float* __restrict__ b,
                                 float* __restrict__ xn) {
    int row = blockIdx.x;                  // 4096 rows
    const float* xr = x + (size_t)row * CC;
    float s = 0.f, s2 = 0.f;
    for (int c = threadIdx.x; c < CC; c += 256) {
        float v = xr[c];
        s += v; s2 += v * v;
    }
    __shared__ float sh_s[8], sh_s2[8];
    for (int o = 16; o > 0; o >>= 1) {
        s  += __shfl_xor_sync(0xffffffffu, s,  o);
        s2 += __shfl_xor_sync(0xffffffffu, s2, o);
    }
    int warp = threadIdx.x >> 5, lane = threadIdx.x & 31;
    if (lane == 0) { sh_s[warp] = s; sh_s2[warp] = s2; }
    __syncthreads();
    if (warp == 0) {
        s  = (lane < 8) ? sh_s[lane]  : 0.f;
        s2 = (lane < 8) ? sh_s2[lane] : 0.f;
        for (int o = 4; o > 0; o >>= 1) {
            s  += __shfl_xor_sync(0xffffffffu, s,  o);
            s2 += __shfl_xor_sync(0xffffffffu, s2, o);
        }
        if (lane == 0) { sh_s[0] = s; sh_s2[0] = s2; }
    }
    __syncthreads();
    float mu  = sh_s[0] * (1.f / CC);
    float var = sh_s2[0] * (1.f / CC) - mu * mu;
    float inv = rsqrtf(var + 1e-6f);
    float* xo = xn + (size_t)row * CC;
    for (int c = threadIdx.x; c < CC; c += 256)
        xo[c] = (xr[c] - mu) * inv * w[c] + b[c];
}

// ---------------- generic SGEMM with fused epilogues ----------------
// C[m,n] = act( sum_k A[m,k]*W[k,n] + bias[n] ) (+ resid[m,n])
// a_perm: A row gather within 1024-blocks (spiral gather)
// o_perm: output row scatter within 1024-blocks (spiral scatter), o_coloff column offset
// act: 0 none, 1 gelu(exact), 2 softplus
#define GBM 128
#define GBN 128
#define GBK 16
__global__ __launch_bounds__(256)
void sgemm_kernel(const float* __restrict__ A, int lda,
                  const float* __restrict__ W,
                  const float* __restrict__ bias,
                  float* __restrict__ Cout, int ldo,
                  int M, int Nn, int Kk,
                  const int* __restrict__ a_perm,
                  const int* __restrict__ o_perm,
                  int o_coloff, int act,
                  const float* __restrict__ resid) {
    __shared__ float As[GBK][GBM + 4];
    __shared__ float Bs[GBK][GBN];
    int tid = threadIdx.x;
    int row0 = blockIdx.y * GBM, col0 = blockIdx.x * GBN;
    int tx = tid & 15, ty = tid >> 4;
    float acc[8][8];
#pragma unroll
    for (int i = 0; i < 8; i++)
#pragma unroll
        for (int j = 0; j < 8; j++) acc[i][j] = 0.f;

    for (int k0 = 0; k0 < Kk; k0 += GBK) {
#pragma unroll
        for (int i = 0; i < 8; i++) {
            int t = tid + i * 256;
            int r = t >> 4, c = t & 15;          // r: 0..127, c: 0..15
            int gr = row0 + r, gk = k0 + c;
            float v = 0.f;
            if (gk < Kk) {
                int arow = gr;
                if (a_perm) arow = (gr & ~(LL - 1)) + a_perm[gr & (LL - 1)];
                v = A[(size_t)arow * lda + gk];
            }
            As[c][r] = v;
        }
#pragma unroll
        for (int i = 0; i < 8; i++) {
            int t = tid + i * 256;
            int r = t >> 7, c = t & 127;         // r: 0..15, c: 0..127
            int gk = k0 + r, gc = col0 + c;
            Bs[r][c] = (gk < Kk && gc < Nn) ? W[(size_t)gk * Nn + gc] : 0.f;
        }
        __syncthreads();
#pragma unroll
        for (int k = 0; k < GBK; k++) {
            float a[8], b[8];
#pragma unroll
            for (int i = 0; i < 8; i++) a[i] = As[k][ty * 8 + i];
#pragma unroll
            for (int j = 0; j < 8; j++) b[j] = Bs[k][tx * 8 + j];
#pragma unroll
            for (int i = 0; i < 8; i++)
#pragma unroll
                for (int j = 0; j < 8; j++)
                    acc[i][j] = fmaf(a[i], b[j], acc[i][j]);
        }
        __syncthreads();
    }

#pragma unroll
    for (int i = 0; i < 8; i++) {
        int gr = row0 + ty * 8 + i;
        int orow = gr;
        if (o_perm) orow = (gr & ~(LL - 1)) + o_perm[gr & (LL - 1)];
#pragma unroll
        for (int j = 0; j < 8; j++) {
            int gc = col0 + tx * 8 + j;
            if (gc >= Nn) continue;
            float v = acc[i][j];
            if (bias) v += bias[gc];
            if (act == 1) {                      // exact GELU
                v = 0.5f * v * (1.f + erff(v * 0.70710678118654752f));
            } else if (act == 2) {               // softplus
                v = (v > 20.f) ? v : log1pf(expf(v));
            }
            if (resid) v += resid[(size_t)gr * Nn + gc];
            Cout[(size_t)orow * ldo + o_coloff + gc] = v;
        }
    }
}

// ---------------- causal depthwise conv (K=4) + SiLU ----------------
__global__ void conv_silu_kernel(const float* __restrict__ xz,
                                 const float* __restrict__ conv_w,
                                 const float* __restrict__ conv_b,
                                 float* __restrict__ uc) {
    int t = blockIdx.x * blockDim.x + threadIdx.x;
    if (t >= MTOT * CC) return;
    int d = t % CC;
    int m = t / CC;
    int l = m & (LL - 1);
    float acc = conv_b[d];
#pragma unroll
    for (int k = 0; k < KK; k++) {
        int ls = l - (KK - 1) + k;
        if (ls >= 0) acc = fmaf(conv_w[d * KK + k],
                                xz[(size_t)(m - (KK - 1) + k) * (2 * CC) + d], acc);
    }
    float s = 1.f / (1.f + expf(-acc));
    uc[t] = acc * s;
}

// ---------------- selective scan ----------------
// 16 lanes = state dim; each 16-lane group owns one (b,d) channel; serial over L.
__global__ __launch_bounds__(128)
void scan_kernel(const float* __restrict__ dt,
                 const float* __restrict__ dbl,
                 const float* __restrict__ uc,
                 const float* __restrict__ xz,
                 const float* __restrict__ A_log,
                 const float* __restrict__ D,
                 float* __restrict__ y) {
    int g = blockIdx.x * 8 + (threadIdx.x >> 4);   // 0..3071
    int n = threadIdx.x & 15;
    int b = g / CC, d = g % CC;
    float a  = -expf(A_log[d * NN + n]);
    float Dv = D[d];
    size_t base = (size_t)b * LL;
    float h = 0.f;
#pragma unroll 4
    for (int l = 0; l < LL; l++) {
        size_t m = base + l;
        float dtv = dt[m * CC + d];
        float uv  = uc[m * CC + d];
        float bv  = dbl[m * DBLC + DR + n];
        float cv  = dbl[m * DBLC + DR + NN + n];
        float dA  = __expf(dtv * a);
        h = fmaf(h, dA, dtv * bv * uv);
        float yp = h * cv;
        yp += __shfl_xor_sync(0xffffffffu, yp, 1);
        yp += __shfl_xor_sync(0xffffffffu, yp, 2);
        yp += __shfl_xor_sync(0xffffffffu, yp, 4);
        yp += __shfl_xor_sync(0xffffffffu, yp, 8);
        if (n == 0) {
            float zv = xz[m * (2 * CC) + CC + d];
            float sz = zv / (1.f + expf(-zv));
            y[m * CC + d] = (yp + Dv * uv) * sz;
        }
    }
}

// ---------------- host side ----------------
static void run_branch(const float* xn, const int* idx,
                       const float* in_w, const float* conv_w, const float* conv_b,
                       const float* xproj_w, const float* dtp_w, const float* dtp_b,
                       const float* A_log, const float* Dd, const float* out_w,
                       float* xz, float* uc, float* dbl, float* dt, float* y,
                       float* fused, int coloff) {
    dim3 thr(256);
    // in_proj with spiral gather:  (4096x768)@(768x1536)
    sgemm_kernel<<<dim3((2*CC + GBN - 1)/GBN, MTOT/GBM), thr>>>(
        xn, CC, in_w, nullptr, xz, 2*CC, MTOT, 2*CC, CC, idx, nullptr, 0, 0, nullptr);
    // causal conv + silu
    conv_silu_kernel<<<(MTOT*CC + 255)/256, thr>>>(xz, conv_w, conv_b, uc);
    // xproj: (4096x768)@(768x80)
    sgemm_kernel<<<dim3(1, MTOT/GBM), thr>>>(
        uc, CC, xproj_w, nullptr, dbl, DBLC, MTOT, DBLC, CC,
        nullptr, nullptr, 0, 0, nullptr);
    // dt proj + softplus: (4096x48)@(48x768)
    sgemm_kernel<<<dim3((CC + GBN - 1)/GBN, MTOT/GBM), thr>>>(
        dbl, DBLC, dtp_w, dtp_b, dt, CC, MTOT, CC, DR,
        nullptr, nullptr, 0, 2, nullptr);
    // selective scan (+ D*u, * silu(z))
    scan_kernel<<<(BB*CC)/8, 128>>>(dt, dbl, uc, xz, A_log, Dd, y);
    // out proj with spiral scatter into concat buffer
    sgemm_kernel<<<dim3((CC + GBN - 1)/GBN, MTOT/GBM), thr>>>(
        y, CC, out_w, nullptr, fused, 2*CC, MTOT, CC, CC,
        nullptr, idx, coloff, 0, nullptr);
}

extern "C" void kernel_launch(void* const* d_in, const int* in_sizes, int n_in,
                              void* d_out, int out_size) {
    const float* x       = (const float*)d_in[0];
    const float* norm_w  = (const float*)d_in[1];
    const float* norm_b  = (const float*)d_in[2];
    const float* fus_w1  = (const float*)d_in[21];
    const float* fus_b1  = (const float*)d_in[22];
    const float* fus_w2  = (const float*)d_in[23];
    const float* fus_b2  = (const float*)d_in[24];
    float* out = (float*)d_out;

    float *xn, *xz, *uc, *dbl, *dt, *y, *fused, *hbuf;
    int *idx_cw, *idx_ccw;
    cudaGetSymbolAddress((void**)&xn,    g_xn);
    cudaGetSymbolAddress((void**)&xz,    g_xz);
    cudaGetSymbolAddress((void**)&uc,    g_uc);
    cudaGetSymbolAddress((void**)&dbl,   g_dbl);
    cudaGetSymbolAddress((void**)&dt,    g_dt);
    cudaGetSymbolAddress((void**)&y,     g_y);
    cudaGetSymbolAddress((void**)&fused, g_fused);
    cudaGetSymbolAddress((void**)&hbuf,  g_h);
    cudaGetSymbolAddress((void**)&idx_cw,  g_idx_cw);
    cudaGetSymbolAddress((void**)&idx_ccw, g_idx_ccw);

    spiral_idx_kernel<<<1, LL>>>(idx_cw, idx_ccw);
    layernorm_kernel<<<MTOT, 256>>>(x, norm_w, norm_b, xn);

    // clockwise branch (inputs 3..11), scatter into fused[:, 0:768]
    run_branch(xn, idx_cw,
               (const float*)d_in[3], (const float*)d_in[4], (const float*)d_in[5],
               (const float*)d_in[6], (const float*)d_in[7], (const float*)d_in[8],
               (const float*)d_in[9], (const float*)d_in[10], (const float*)d_in[11],
               xz, uc, dbl, dt, y, fused, 0);
    // counter-clockwise branch (inputs 12..20), scatter into fused[:, 768:1536]
    run_branch(xn, idx_ccw,
               (const float*)d_in[12], (const float*)d_in[13], (const float*)d_in[14],
               (const float*)d_in[15], (const float*)d_in[16], (const float*)d_in[17],
               (const float*)d_in[18], (const float*)d_in[19], (const float*)d_in[20],
               xz, uc, dbl, dt, y, fused, CC);

    dim3 thr(256);
    // fus1: (4096x1536)@(1536x768) + b1, exact GELU
    sgemm_kernel<<<dim3((CC + GBN - 1)/GBN, MTOT/GBM), thr>>>(
        fused, 2*CC, fus_w1, fus_b1, hbuf, CC, MTOT, CC, 2*CC,
        nullptr, nullptr, 0, 1, nullptr);
    // fus2: (4096x768)@(768x768) + b2 + residual x
    sgemm_kernel<<<dim3((CC + GBN - 1)/GBN, MTOT/GBM), thr>>>(
        hbuf, CC, fus_w2, fus_b2, out, CC, MTOT, CC, CC,
        nullptr, nullptr, 0, 0, x);
}

// round 4
// speedup vs baseline: 1.4792x; 1.4792x over previous
#include <cuda_runtime.h>
#include <cuda_bf16.h>
#include <cstdint>

// Problem constants (fixed by the dataset)
#define BB 4
#define LL 1024
#define HH 32
#define WW 32
#define CC 768
#define NN 16
#define DR 48
#define KK 4
#define MTOT (BB*LL)          // 4096
#define DBLC (DR + 2*NN)      // 80

// ---------------- scratch (no allocations allowed) ----------------
__device__ float g_xn   [MTOT*CC];
__device__ float g_xz   [MTOT*2*CC];
__device__ float g_uc   [MTOT*CC];
__device__ float g_dbl  [MTOT*DBLC];
__device__ float g_dt   [MTOT*CC];
__device__ float g_y    [MTOT*CC];
__device__ float g_fused[MTOT*2*CC];
__device__ float g_h    [MTOT*CC];
__device__ int   g_idx_cw [LL];
__device__ int   g_idx_ccw[LL];

// ---------------- spiral index generation ----------------
__global__ void spiral_idx_kernel(int* idx_cw, int* idx_ccw) {
    int cell = threadIdx.x;            // 1024 threads
    int i = cell / WW, j = cell % WW;
    int r = min(min(i, j), min(HH - 1 - i, WW - 1 - j));
    int h = HH - 2 * r, w = WW - 2 * r;
    int prior = HH * WW - h * w;
    int pos;
    if (i == r)                pos = j - r;
    else if (j == WW - 1 - r)  pos = (w - 1) + (i - r);
    else if (i == HH - 1 - r)  pos = (w - 1) + (h - 1) + (WW - 1 - r - j);
    else                       pos = 2*(w - 1) + (h - 1) + (HH - 1 - r - i);
    idx_cw[prior + pos] = cell;
    if (i == r)                pos = (WW - 1 - r) - j;
    else if (j == r)           pos = (w - 1) + (i - r);
    else if (i == HH - 1 - r)  pos = (w - 1) + (h - 1) + (j - r);
    else                       pos = 2*(w - 1) + (h - 1) + (HH - 1 - r - i);
    idx_ccw[prior + pos] = cell;
}

// ---------------- layernorm ----------------
__global__ void layernorm_kernel(const float* __restrict__ x,
                                 const float* __restrict__ w,
                                 const float* __restrict__ b,
                                 float* __restrict__ xn) {
    int row = blockIdx.x;
    const float* xr = x + (size_t)row * CC;
    float s = 0.f, s2 = 0.f;
    for (int c = threadIdx.x; c < CC; c += 256) {
        float v = xr[c];
        s += v; s2 += v * v;
    }
    __shared__ float sh_s[8], sh_s2[8];
    for (int o = 16; o > 0; o >>= 1) {
        s  += __shfl_xor_sync(0xffffffffu, s,  o);
        s2 += __shfl_xor_sync(0xffffffffu, s2, o);
    }
    int warp = threadIdx.x >> 5, lane = threadIdx.x & 31;
    if (lane == 0) { sh_s[warp] = s; sh_s2[warp] = s2; }
    __syncthreads();
    if (warp == 0) {
        s  = (lane < 8) ? sh_s[lane]  : 0.f;
        s2 = (lane < 8) ? sh_s2[lane] : 0.f;
        for (int o = 4; o > 0; o >>= 1) {
            s  += __shfl_xor_sync(0xffffffffu, s,  o);
            s2 += __shfl_xor_sync(0xffffffffu, s2, o);
        }
        if (lane == 0) { sh_s[0] = s; sh_s2[0] = s2; }
    }
    __syncthreads();
    float mu  = sh_s[0] * (1.f / CC);
    float var = sh_s2[0] * (1.f / CC) - mu * mu;
    float inv = rsqrtf(var + 1e-6f);
    float* xo = xn + (size_t)row * CC;
    for (int c = threadIdx.x; c < CC; c += 256)
        xo[c] = (xr[c] - mu) * inv * w[c] + b[c];
}

// ---------------- TF32 tensor-core GEMM with fused epilogues ----------------
// C[m,n] = act( sum_k A[m,k]*W[k,n] + bias[n] ) (+ resid[m,n])
// BM=BN=128, BK=16, 256 threads, warp grid 2x4, warp tile 64x32 (m16n8k8 frags)
#define AP 20            // As row pitch (floats) — conflict-free & 16B-aligned
#define BP 136           // Bs row pitch (floats) — conflict-free & 16B-aligned
#define ABUF (128*AP)
#define BBUF (16*BP)

__device__ __forceinline__ uint32_t f2tf(float f) {
    uint32_t r; asm("cvt.rna.tf32.f32 %0, %1;" : "=r"(r) : "f"(f)); return r;
}
__device__ __forceinline__ void cp16(uint32_t dst, const float* src, int sz) {
    asm volatile("cp.async.cg.shared.global [%0], [%1], 16, %2;\n"
                 :: "r"(dst), "l"(src), "r"(sz));
}

__global__ __launch_bounds__(256, 2)
void tf32gemm_kernel(const float* __restrict__ A, int lda,
                     const float* __restrict__ W,
                     const float* __restrict__ bias,
                     float* __restrict__ Cout, int ldo,
                     int Nn, int Kk,
                     const int* __restrict__ a_perm,
                     const int* __restrict__ o_perm,
                     int o_coloff, int act,
                     const float* __restrict__ resid) {
    __shared__ float As[2*ABUF];
    __shared__ float Bs[2*BBUF];
    int tid = threadIdx.x;
    int row0 = blockIdx.y * 128, col0 = blockIdx.x * 128;
    int warp = tid >> 5, lane = tid & 31;
    int wm = warp >> 2, wn = warp & 3;          // 2 x 4 warp grid
    int g = lane >> 2, t4 = lane & 3;

    // ---- global source mapping (2 x 16B chunks per thread for A and for B)
    int ar0 = tid >> 2, ar1 = ar0 + 64, ac = (tid & 3) * 4;
    int gr0 = row0 + ar0, gr1 = row0 + ar1;
    if (a_perm) {
        gr0 = (gr0 & ~(LL - 1)) + a_perm[gr0 & (LL - 1)];
        gr1 = (gr1 & ~(LL - 1)) + a_perm[gr1 & (LL - 1)];
    }
    const float* apt0 = A + (size_t)gr0 * lda + ac;
    const float* apt1 = A + (size_t)gr1 * lda + ac;
    uint32_t asb = (uint32_t)__cvta_generic_to_shared(As);
    uint32_t bsb = (uint32_t)__cvta_generic_to_shared(Bs);
    uint32_t dA0 = asb + (ar0 * AP + ac) * 4;
    uint32_t dA1 = asb + (ar1 * AP + ac) * 4;

    int bk0 = tid >> 5, bk1 = bk0 + 8, bc = (tid & 31) * 4;
    int gn = col0 + bc;
    int szB = (gn < Nn) ? 16 : 0;
    const float* bpt0 = W + (size_t)bk0 * Nn + (szB ? gn : 0);
    const float* bpt1 = W + (size_t)bk1 * Nn + (szB ? gn : 0);
    uint32_t dB0 = bsb + (bk0 * BP + bc) * 4;
    uint32_t dB1 = bsb + (bk1 * BP + bc) * 4;

    float acc[4][4][4];
#pragma unroll
    for (int i = 0; i < 4; i++)
#pragma unroll
        for (int j = 0; j < 4; j++)
#pragma unroll
            for (int q = 0; q < 4; q++) acc[i][j][q] = 0.f;

    int ntiles = Kk >> 4;
    // preload tile 0
    cp16(dA0, apt0, 16); cp16(dA1, apt1, 16);
    cp16(dB0, bpt0, szB); cp16(dB1, bpt1, szB);
    asm volatile("cp.async.commit_group;\n");

    for (int t = 0; t < ntiles; t++) {
        int buf = t & 1;
        if (t + 1 < ntiles) {
            int nb = (t + 1) & 1, k0 = (t + 1) * 16;
            cp16(dA0 + nb * ABUF * 4, apt0 + k0, 16);
            cp16(dA1 + nb * ABUF * 4, apt1 + k0, 16);
            cp16(dB0 + nb * BBUF * 4, bpt0 + (size_t)k0 * Nn, szB);
            cp16(dB1 + nb * BBUF * 4, bpt1 + (size_t)k0 * Nn, szB);
            asm volatile("cp.async.commit_group;\n");
            asm volatile("cp.async.wait_group 1;\n");
        } else {
            asm volatile("cp.async.wait_group 0;\n");
        }
        __syncthreads();
        const float* as = As + buf * ABUF;
        const float* bs = Bs + buf * BBUF;
#pragma unroll
        for (int kk = 0; kk < 16; kk += 8) {
            uint32_t af[4][4], bf[4][2];
#pragma unroll
            for (int mi = 0; mi < 4; mi++) {
                int rb = (wm * 64 + mi * 16 + g) * AP + kk + t4;
                af[mi][0] = f2tf(as[rb]);
                af[mi][1] = f2tf(as[rb + 8 * AP]);
                af[mi][2] = f2tf(as[rb + 4]);
                af[mi][3] = f2tf(as[rb + 8 * AP + 4]);
            }
#pragma unroll
            for (int ni = 0; ni < 4; ni++) {
                int cb = (kk + t4) * BP + wn * 32 + ni * 8 + g;
                bf[ni][0] = f2tf(bs[cb]);
                bf[ni][1] = f2tf(bs[cb + 4 * BP]);
            }
#pragma unroll
            for (int mi = 0; mi < 4; mi++)
#pragma unroll
                for (int ni = 0; ni < 4; ni++)
                    asm volatile(
                        "mma.sync.aligned.m16n8k8.row.col.f32.tf32.tf32.f32 "
                        "{%0,%1,%2,%3}, {%4,%5,%6,%7}, {%8,%9}, {%0,%1,%2,%3};\n"
                        : "+f"(acc[mi][ni][0]), "+f"(acc[mi][ni][1]),
                          "+f"(acc[mi][ni][2]), "+f"(acc[mi][ni][3])
                        : "r"(af[mi][0]), "r"(af[mi][1]), "r"(af[mi][2]), "r"(af[mi][3]),
                          "r"(bf[ni][0]), "r"(bf[ni][1]));
        }
        __syncthreads();
    }

    // ---- epilogue: c0/c1 -> (row g, col 2t,2t+1), c2/c3 -> (row g+8, ...)
#pragma unroll
    for (int mi = 0; mi < 4; mi++) {
#pragma unroll
        for (int half = 0; half < 2; half++) {
            int grow = row0 + wm * 64 + mi * 16 + g + half * 8;
            int orow = grow;
            if (o_perm) orow = (grow & ~(LL - 1)) + o_perm[grow & (LL - 1)];
#pragma unroll
            for (int ni = 0; ni < 4; ni++) {
                int gc = col0 + wn * 32 + ni * 8 + 2 * t4;
                if (gc >= Nn) continue;
                float v0 = acc[mi][ni][half * 2 + 0];
                float v1 = acc[mi][ni][half * 2 + 1];
                if (bias) { v0 += bias[gc]; v1 += bias[gc + 1]; }
                if (act == 1) {                       // exact GELU
                    v0 = 0.5f * v0 * (1.f + erff(v0 * 0.70710678118654752f));
                    v1 = 0.5f * v1 * (1.f + erff(v1 * 0.70710678118654752f));
                } else if (act == 2) {                // softplus
                    v0 = (v0 > 20.f) ? v0 : log1pf(expf(v0));
                    v1 = (v1 > 20.f) ? v1 : log1pf(expf(v1));
                }
                if (resid) {
                    v0 += resid[(size_t)grow * Nn + gc];
                    v1 += resid[(size_t)grow * Nn + gc + 1];
                }
                float2* p = (float2*)(Cout + (size_t)orow * ldo + o_coloff + gc);
                *p = make_float2(v0, v1);
            }
        }
    }
}

// ---------------- causal depthwise conv (K=4) + SiLU ----------------
__global__ void conv_silu_kernel(const float* __restrict__ xz,
                                 const float* __restrict__ conv_w,
                                 const float* __restrict__ conv_b,
                                 float* __restrict__ uc) {
    int t = blockIdx.x * blockDim.x + threadIdx.x;
    if (t >= MTOT * CC) return;
    int d = t % CC;
    int m = t / CC;
    int l = m & (LL - 1);
    float acc = conv_b[d];
#pragma unroll
    for (int k = 0; k < KK; k++) {
        int ls = l - (KK - 1) + k;
        if (ls >= 0) acc = fmaf(conv_w[d * KK + k],
                                xz[(size_t)(m - (KK - 1) + k) * (2 * CC) + d], acc);
    }
    float s = 1.f / (1.f + expf(-acc));
    uc[t] = acc * s;
}

// ---------------- selective scan ----------------
__global__ __launch_bounds__(128)
void scan_kernel(const float* __restrict__ dt,
                 const float* __restrict__ dbl,
                 const float* __restrict__ uc,
                 const float* __restrict__ xz,
                 const float* __restrict__ A_log,
                 const float* __restrict__ D,
                 float* __restrict__ y) {
    int g = blockIdx.x * 8 + (threadIdx.x >> 4);   // 0..3071
    int n = threadIdx.x & 15;
    int b = g / CC, d = g % CC;
    float a  = -expf(A_log[d * NN + n]);
    float Dv = D[d];
    size_t base = (size_t)b * LL;
    float h = 0.f;
#pragma unroll 4
    for (int l = 0; l < LL; l++) {
        size_t m = base + l;
        float dtv = dt[m * CC + d];
        float uv  = uc[m * CC + d];
        float bv  = dbl[m * DBLC + DR + n];
        float cv  = dbl[m * DBLC + DR + NN + n];
        float dA  = __expf(dtv * a);
        h = fmaf(h, dA, dtv * bv * uv);
        float yp = h * cv;
        yp += __shfl_xor_sync(0xffffffffu, yp, 1);
        yp += __shfl_xor_sync(0xffffffffu, yp, 2);
        yp += __shfl_xor_sync(0xffffffffu, yp, 4);
        yp += __shfl_xor_sync(0xffffffffu, yp, 8);
        if (n == 0) {
            float zv = xz[m * (2 * CC) + CC + d];
            float sz = zv / (1.f + expf(-zv));
            y[m * CC + d] = (yp + Dv * uv) * sz;
        }
    }
}

// ---------------- host side ----------------
static void run_branch(const float* xn, const int* idx,
                       const float* in_w, const float* conv_w, const float* conv_b,
                       const float* xproj_w, const float* dtp_w, const float* dtp_b,
                       const float* A_log, const float* Dd, const float* out_w,
                       float* xz, float* uc, float* dbl, float* dt, float* y,
                       float* fused, int coloff) {
    dim3 thr(256);
    // in_proj with spiral gather:  (4096x768)@(768x1536)
    tf32gemm_kernel<<<dim3(12, 32), thr>>>(
        xn, CC, in_w, nullptr, xz, 2*CC, 2*CC, CC, idx, nullptr, 0, 0, nullptr);
    // causal conv + silu
    conv_silu_kernel<<<(MTOT*CC + 255)/256, thr>>>(xz, conv_w, conv_b, uc);
    // xproj: (4096x768)@(768x80)
    tf32gemm_kernel<<<dim3(1, 32), thr>>>(
        uc, CC, xproj_w, nullptr, dbl, DBLC, DBLC, CC,
        nullptr, nullptr, 0, 0, nullptr);
    // dt proj + softplus: (4096x48)@(48x768)
    tf32gemm_kernel<<<dim3(6, 32), thr>>>(
        dbl, DBLC, dtp_w, dtp_b, dt, CC, CC, DR,
        nullptr, nullptr, 0, 2, nullptr);
    // selective scan (+ D*u, * silu(z))
    scan_kernel<<<(BB*CC)/8, 128>>>(dt, dbl, uc, xz, A_log, Dd, y);
    // out proj with spiral scatter into concat buffer
    tf32gemm_kernel<<<dim3(6, 32), thr>>>(
        y, CC, out_w, nullptr, fused, 2*CC, CC, CC,
        nullptr, idx, coloff, 0, nullptr);
}

extern "C" void kernel_launch(void* const* d_in, const int* in_sizes, int n_in,
                              void* d_out, int out_size) {
    const float* x       = (const float*)d_in[0];
    const float* norm_w  = (const float*)d_in[1];
    const float* norm_b  = (const float*)d_in[2];
    const float* fus_w1  = (const float*)d_in[21];
    const float* fus_b1  = (const float*)d_in[22];
    const float* fus_w2  = (const float*)d_in[23];
    const float* fus_b2  = (const float*)d_in[24];
    float* out = (float*)d_out;

    float *xn, *xz, *uc, *dbl, *dt, *y, *fused, *hbuf;
    int *idx_cw, *idx_ccw;
    cudaGetSymbolAddress((void**)&xn,    g_xn);
    cudaGetSymbolAddress((void**)&xz,    g_xz);
    cudaGetSymbolAddress((void**)&uc,    g_uc);
    cudaGetSymbolAddress((void**)&dbl,   g_dbl);
    cudaGetSymbolAddress((void**)&dt,    g_dt);
    cudaGetSymbolAddress((void**)&y,     g_y);
    cudaGetSymbolAddress((void**)&fused, g_fused);
    cudaGetSymbolAddress((void**)&hbuf,  g_h);
    cudaGetSymbolAddress((void**)&idx_cw,  g_idx_cw);
    cudaGetSymbolAddress((void**)&idx_ccw, g_idx_ccw);

    spiral_idx_kernel<<<1, LL>>>(idx_cw, idx_ccw);
    layernorm_kernel<<<MTOT, 256>>>(x, norm_w, norm_b, xn);

    // clockwise branch (inputs 3..11), scatter into fused[:, 0:768]
    run_branch(xn, idx_cw,
               (const float*)d_in[3], (const float*)d_in[4], (const float*)d_in[5],
               (const float*)d_in[6], (const float*)d_in[7], (const float*)d_in[8],
               (const float*)d_in[9], (const float*)d_in[10], (const float*)d_in[11],
               xz, uc, dbl, dt, y, fused, 0);
    // counter-clockwise branch (inputs 12..20), scatter into fused[:, 768:1536]
    run_branch(xn, idx_ccw,
               (const float*)d_in[12], (const float*)d_in[13], (const float*)d_in[14],
               (const float*)d_in[15], (const float*)d_in[16], (const float*)d_in[17],
               (const float*)d_in[18], (const float*)d_in[19], (const float*)d_in[20],
               xz, uc, dbl, dt, y, fused, CC);

    dim3 thr(256);
    // fus1: (4096x1536)@(1536x768) + b1, exact GELU
    tf32gemm_kernel<<<dim3(6, 32), thr>>>(
        fused, 2*CC, fus_w1, fus_b1, hbuf, CC, CC, 2*CC,
        nullptr, nullptr, 0, 1, nullptr);
    // fus2: (4096x768)@(768x768) + b2 + residual x
    tf32gemm_kernel<<<dim3(6, 32), thr>>>(
        hbuf, CC, fus_w2, fus_b2, out, CC, CC, CC,
        nullptr, nullptr, 0, 0, x);
}

// round 6
// speedup vs baseline: 2.6246x; 1.7743x over previous
#include <cuda_runtime.h>
#include <cuda_bf16.h>
#include <cstdint>

// Problem constants (fixed by the dataset)
#define BB 4
#define LL 1024
#define HH 32
#define WW 32
#define CC 768
#define NN 16
#define DR 48
#define KK 4
#define MTOT (BB*LL)          // 4096
#define DBLC (DR + 2*NN)      // 80

// ---------------- scratch (no allocations allowed) ----------------
__device__ __nv_bfloat16 g_xn16[MTOT*CC];
__device__ float         g_xz  [2][MTOT*2*CC];
__device__ float         g_uc  [2][MTOT*CC];
__device__ __nv_bfloat16 g_uc16[2][MTOT*CC];
__device__ float         g_dbl [2][MTOT*DBLC];
__device__ __nv_bfloat16 g_dbl16[2][MTOT*DBLC];
__device__ float         g_dt  [2][MTOT*CC];
__device__ __nv_bfloat16 g_y16 [2][MTOT*CC];
__device__ __nv_bfloat16 g_fused16[MTOT*2*CC];
__device__ __nv_bfloat16 g_h16 [MTOT*CC];
__device__ int g_idx_cw [LL];
__device__ int g_idx_ccw[LL];
// bf16 transposed weights Wt[n][k]
__device__ __nv_bfloat16 g_inwt [2][2*CC*CC];   // [1536][768]
__device__ __nv_bfloat16 g_xpt  [2][DBLC*CC];   // [80][768]
__device__ __nv_bfloat16 g_dtpt [2][CC*DR];     // [768][48]
__device__ __nv_bfloat16 g_outwt[2][CC*CC];     // [768][768]
__device__ __nv_bfloat16 g_fw1t [CC*2*CC];      // [768][1536]
__device__ __nv_bfloat16 g_fw2t [CC*CC];        // [768][768]

// ---------------- spiral index generation ----------------
__global__ void spiral_idx_kernel(int* idx_cw, int* idx_ccw) {
    int cell = threadIdx.x;
    int i = cell / WW, j = cell % WW;
    int r = min(min(i, j), min(HH - 1 - i, WW - 1 - j));
    int h = HH - 2 * r, w = WW - 2 * r;
    int prior = HH * WW - h * w;
    int pos;
    if (i == r)                pos = j - r;
    else if (j == WW - 1 - r)  pos = (w - 1) + (i - r);
    else if (i == HH - 1 - r)  pos = (w - 1) + (h - 1) + (WW - 1 - r - j);
    else                       pos = 2*(w - 1) + (h - 1) + (HH - 1 - r - i);
    idx_cw[prior + pos] = cell;
    if (i == r)                pos = (WW - 1 - r) - j;
    else if (j == r)           pos = (w - 1) + (i - r);
    else if (i == HH - 1 - r)  pos = (w - 1) + (h - 1) + (j - r);
    else                       pos = 2*(w - 1) + (h - 1) + (HH - 1 - r - i);
    idx_ccw[prior + pos] = cell;
}

// ---------------- weight transpose+convert: in[K][N] f32 -> out[N][K] bf16 ----------------
struct WDesc { const float* in; __nv_bfloat16* out; int K; int N; };
struct WAll { WDesc w[10]; };
__global__ void wt_kernel(WAll all) {
    WDesc d = all.w[blockIdx.z];
    int n0 = blockIdx.x * 32, k0 = blockIdx.y * 32;
    if (n0 >= d.N || k0 >= d.K) return;
    __shared__ float t[32][33];
    int tx = threadIdx.x, ty = threadIdx.y;          // 32 x 8
#pragma unroll
    for (int i = 0; i < 32; i += 8) {
        int k = k0 + ty + i, n = n0 + tx;
        t[ty + i][tx] = (k < d.K && n < d.N) ? d.in[(size_t)k * d.N + n] : 0.f;
    }
    __syncthreads();
#pragma unroll
    for (int i = 0; i < 32; i += 8) {
        int n = n0 + ty + i, k = k0 + tx;
        if (n < d.N && k < d.K) d.out[(size_t)n * d.K + k] = __float2bfloat16(t[tx][ty + i]);
    }
}

// ---------------- layernorm -> bf16 ----------------
__global__ void layernorm_kernel(const float* __restrict__ x,
                                 const float* __restrict__ w,
                                 const float* __restrict__ b) {
    int row = blockIdx.x;
    const float* xr = x + (size_t)row * CC;
    float s = 0.f, s2 = 0.f;
    for (int c = threadIdx.x; c < CC; c += 256) {
        float v = xr[c];
        s += v; s2 += v * v;
    }
    __shared__ float sh_s[8], sh_s2[8];
    for (int o = 16; o > 0; o >>= 1) {
        s  += __shfl_xor_sync(0xffffffffu, s,  o);
        s2 += __shfl_xor_sync(0xffffffffu, s2, o);
    }
    int warp = threadIdx.x >> 5, lane = threadIdx.x & 31;
    if (lane == 0) { sh_s[warp] = s; sh_s2[warp] = s2; }
    __syncthreads();
    if (warp == 0) {
        s  = (lane < 8) ? sh_s[lane]  : 0.f;
        s2 = (lane < 8) ? sh_s2[lane] : 0.f;
        for (int o = 4; o > 0; o >>= 1) {
            s  += __shfl_xor_sync(0xffffffffu, s,  o);
            s2 += __shfl_xor_sync(0xffffffffu, s2, o);
        }
        if (lane == 0) { sh_s[0] = s; sh_s2[0] = s2; }
    }
    __syncthreads();
    float mu  = sh_s[0] * (1.f / CC);
    float var = sh_s2[0] * (1.f / CC) - mu * mu;
    float inv = rsqrtf(var + 1e-6f);
    for (int c = threadIdx.x; c < CC; c += 256)
        g_xn16[(size_t)row * CC + c] = __float2bfloat16((xr[c] - mu) * inv * w[c] + b[c]);
}

// ---------------- bf16 tensor-core GEMM with fused epilogues ----------------
// BM=BN=128, BK=32, 256 threads, warp grid 2x4, warp tile 64x32, m16n8k16 bf16
#define APk 40                 // smem pitch in bf16 elems (80 B) — ldmatrix conflict-free
#define ABUFE (128*APk)        // elems per buffer

struct BrArgs {
    const __nv_bfloat16* A;
    const __nv_bfloat16* Wt;       // [n][k]
    const float* bias;
    float* out32;
    __nv_bfloat16* out16;
    const int* a_perm;
    const int* o_perm;
    int o_coloff;
};

__device__ __forceinline__ void cp16(uint32_t dst, const void* src, int sz) {
    asm volatile("cp.async.cg.shared.global [%0], [%1], 16, %2;\n"
                 :: "r"(dst), "l"(src), "r"(sz));
}
__device__ __forceinline__ void ldsm4(uint32_t addr, uint32_t& r0, uint32_t& r1,
                                      uint32_t& r2, uint32_t& r3) {
    asm volatile("ldmatrix.sync.aligned.m8n8.x4.shared.b16 {%0,%1,%2,%3}, [%4];"
                 : "=r"(r0), "=r"(r1), "=r"(r2), "=r"(r3) : "r"(addr));
}

__global__ __launch_bounds__(256)
void bf16gemm_kernel(BrArgs P0, BrArgs P1, int lda, int ldo, int Nn, int Kk,
                     int act, const float* __restrict__ resid) {
    BrArgs P = (blockIdx.z == 0) ? P0 : P1;
    __shared__ __nv_bfloat16 As[2 * ABUFE];
    __shared__ __nv_bfloat16 Bs[2 * ABUFE];
    int tid = threadIdx.x;
    int row0 = blockIdx.y * 128, col0 = blockIdx.x * 128;
    int warp = tid >> 5, lane = tid & 31;
    int wm = warp >> 2, wn = warp & 3;
    int g = lane >> 2, t4 = lane & 3;

    // ---- loader mapping: each thread owns one row-slot, two 8-elem chunks
    int lrow = tid >> 1;                 // 0..127
    int kc0 = (tid & 1) * 16, kc1 = kc0 + 8;
    int garow = row0 + lrow;
    if (P.a_perm) garow = (garow & ~(LL - 1)) + P.a_perm[garow & (LL - 1)];
    const __nv_bfloat16* abase = P.A + (size_t)garow * lda;
    int gn = col0 + lrow;
    const __nv_bfloat16* bbase = P.Wt + (size_t)(gn < Nn ? gn : 0) * Kk;
    bool bok = (gn < Nn);

    uint32_t asb = (uint32_t)__cvta_generic_to_shared(As);
    uint32_t bsb = (uint32_t)__cvta_generic_to_shared(Bs);
    uint32_t dA0 = asb + (lrow * APk + kc0) * 2;
    uint32_t dA1 = asb + (lrow * APk + kc1) * 2;
    uint32_t dB0 = bsb + (lrow * APk + kc0) * 2;
    uint32_t dB1 = bsb + (lrow * APk + kc1) * 2;

    // ---- ldmatrix lane offsets (element offsets, excluding buf & kk)
    uint32_t a_off[4], b_off[2];
    {
        int arl = lane & 15, akhi = (lane >> 4) << 3;
#pragma unroll
        for (int mi = 0; mi < 4; mi++)
            a_off[mi] = ((wm * 64 + mi * 16 + arl) * APk + akhi) * 2;
        int bnr = ((lane >> 4) << 3) + (lane & 7);
        int bkhi = ((lane >> 3) & 1) << 3;
#pragma unroll
        for (int np = 0; np < 2; np++)
            b_off[np] = ((wn * 32 + np * 16 + bnr) * APk + bkhi) * 2;
    }

    float acc[4][4][4];
#pragma unroll
    for (int i = 0; i < 4; i++)
#pragma unroll
        for (int j = 0; j < 4; j++)
#pragma unroll
            for (int q = 0; q < 4; q++) acc[i][j][q] = 0.f;

    int ntiles = (Kk + 31) >> 5;
    // preload tile 0
    {
        int sA0 = (kc0 < Kk) ? 16 : 0, sA1 = (kc1 < Kk) ? 16 : 0;
        cp16(dA0, abase + kc0, sA0);
        cp16(dA1, abase + kc1, sA1);
        cp16(dB0, bbase + kc0, bok ? sA0 : 0);
        cp16(dB1, bbase + kc1, bok ? sA1 : 0);
        asm volatile("cp.async.commit_group;\n");
    }

    for (int t = 0; t < ntiles; t++) {
        int buf = t & 1;
        if (t + 1 < ntiles) {
            int nb = (t + 1) & 1, k0 = (t + 1) * 32;
            uint32_t bo = nb * ABUFE * 2;
            int s0 = (k0 + kc0 < Kk) ? 16 : 0, s1 = (k0 + kc1 < Kk) ? 16 : 0;
            cp16(dA0 + bo, abase + k0 + kc0, s0);
            cp16(dA1 + bo, abase + k0 + kc1, s1);
            cp16(dB0 + bo, bbase + k0 + kc0, bok ? s0 : 0);
            cp16(dB1 + bo, bbase + k0 + kc1, bok ? s1 : 0);
            asm volatile("cp.async.commit_group;\n");
            asm volatile("cp.async.wait_group 1;\n");
        } else {
            asm volatile("cp.async.wait_group 0;\n");
        }
        __syncthreads();
        uint32_t abuf = asb + buf * ABUFE * 2;
        uint32_t bbuf = bsb + buf * ABUFE * 2;
#pragma unroll
        for (int kk = 0; kk < 32; kk += 16) {
            uint32_t af[4][4], bf[4][2];
#pragma unroll
            for (int mi = 0; mi < 4; mi++)
                ldsm4(abuf + kk * 2 + a_off[mi],
                      af[mi][0], af[mi][1], af[mi][2], af[mi][3]);
#pragma unroll
            for (int np = 0; np < 2; np++)
                ldsm4(bbuf + kk * 2 + b_off[np],
                      bf[2*np][0], bf[2*np][1], bf[2*np+1][0], bf[2*np+1][1]);
#pragma unroll
            for (int mi = 0; mi < 4; mi++)
#pragma unroll
                for (int ni = 0; ni < 4; ni++)
                    asm volatile(
                        "mma.sync.aligned.m16n8k16.row.col.f32.bf16.bf16.f32 "
                        "{%0,%1,%2,%3}, {%4,%5,%6,%7}, {%8,%9}, {%0,%1,%2,%3};\n"
                        : "+f"(acc[mi][ni][0]), "+f"(acc[mi][ni][1]),
                          "+f"(acc[mi][ni][2]), "+f"(acc[mi][ni][3])
                        : "r"(af[mi][0]), "r"(af[mi][1]), "r"(af[mi][2]), "r"(af[mi][3]),
                          "r"(bf[ni][0]), "r"(bf[ni][1]));
        }
        __syncthreads();
    }

    // ---- epilogue
#pragma unroll
    for (int mi = 0; mi < 4; mi++) {
#pragma unroll
        for (int half = 0; half < 2; half++) {
            int grow = row0 + wm * 64 + mi * 16 + g + half * 8;
            int orow = grow;
            if (P.o_perm) orow = (grow & ~(LL - 1)) + P.o_perm[grow & (LL - 1)];
#pragma unroll
            for (int ni = 0; ni < 4; ni++) {
                int gc = col0 + wn * 32 + ni * 8 + 2 * t4;
                if (gc >= Nn) continue;
                float v0 = acc[mi][ni][half * 2 + 0];
                float v1 = acc[mi][ni][half * 2 + 1];
                if (P.bias) { v0 += P.bias[gc]; v1 += P.bias[gc + 1]; }
                if (act == 1) {                       // exact GELU
                    v0 = 0.5f * v0 * (1.f + erff(v0 * 0.70710678118654752f));
                    v1 = 0.5f * v1 * (1.f + erff(v1 * 0.70710678118654752f));
                } else if (act == 2) {                // softplus
                    v0 = (v0 > 20.f) ? v0 : log1pf(expf(v0));
                    v1 = (v1 > 20.f) ? v1 : log1pf(expf(v1));
                }
                if (resid) {
                    v0 += resid[(size_t)grow * Nn + gc];
                    v1 += resid[(size_t)grow * Nn + gc + 1];
                }
                size_t oidx = (size_t)orow * ldo + P.o_coloff + gc;
                if (P.out32) *(float2*)(P.out32 + oidx) = make_float2(v0, v1);
                if (P.out16) *(__nv_bfloat162*)(P.out16 + oidx) = __floats2bfloat162_rn(v0, v1);
            }
        }
    }
}

// ---------------- causal depthwise conv (K=4) + SiLU, dual-branch ----------------
__global__ void conv_silu_kernel(const float* __restrict__ cw0, const float* __restrict__ cb0,
                                 const float* __restrict__ cw1, const float* __restrict__ cb1) {
    int br = blockIdx.y;
    const float* xz = g_xz[br];
    const float* cw = br ? cw1 : cw0;
    const float* cb = br ? cb1 : cb0;
    int t = blockIdx.x * blockDim.x + threadIdx.x;
    if (t >= MTOT * CC) return;
    int d = t % CC;
    int m = t / CC;
    int l = m & (LL - 1);
    float acc = cb[d];
#pragma unroll
    for (int k = 0; k < KK; k++) {
        int ls = l - (KK - 1) + k;
        if (ls >= 0) acc = fmaf(cw[d * KK + k],
                                xz[(size_t)(m - (KK - 1) + k) * (2 * CC) + d], acc);
    }
    float s = 1.f / (1.f + expf(-acc));
    float v = acc * s;
    g_uc[br][t] = v;
    g_uc16[br][t] = __float2bfloat16(v);
}

// ---------------- selective scan, dual-branch ----------------
__global__ __launch_bounds__(128)
void scan_kernel(const float* __restrict__ A0, const float* __restrict__ D0,
                 const float* __restrict__ A1, const float* __restrict__ D1) {
    int br = blockIdx.y;
    const float* dt  = g_dt[br];
    const float* dbl = g_dbl[br];
    const float* uc  = g_uc[br];
    const float* xz  = g_xz[br];
    const float* Alog = br ? A1 : A0;
    const float* Dp   = br ? D1 : D0;
    int gidx = blockIdx.x * 8 + (threadIdx.x >> 4);   // 0..3071
    int n = threadIdx.x & 15;
    int b = gidx / CC, d = gidx % CC;
    float a  = -expf(Alog[d * NN + n]);
    float Dv = Dp[d];
    size_t base = (size_t)b * LL;
    float h = 0.f;
#pragma unroll 4
    for (int l = 0; l < LL; l++) {
        size_t m = base + l;
        float dtv = dt[m * CC + d];
        float uv  = uc[m * CC + d];
        float bv  = dbl[m * DBLC + DR + n];
        float cv  = dbl[m * DBLC + DR + NN + n];
        float dA  = __expf(dtv * a);
        h = fmaf(h, dA, dtv * bv * uv);
        float yp = h * cv;
        yp += __shfl_xor_sync(0xffffffffu, yp, 1);
        yp += __shfl_xor_sync(0xffffffffu, yp, 2);
        yp += __shfl_xor_sync(0xffffffffu, yp, 4);
        yp += __shfl_xor_sync(0xffffffffu, yp, 8);
        if (n == 0) {
            float zv = xz[m * (2 * CC) + CC + d];
            float sz = zv / (1.f + expf(-zv));
            g_y16[br][m * CC + d] = __float2bfloat16((yp + Dv * uv) * sz);
        }
    }
}

// ---------------- host side ----------------
template <typename T> static T* sym(const void* s) {
    void* p = nullptr; cudaGetSymbolAddress(&p, s); return (T*)p;
}

extern "C" void kernel_launch(void* const* d_in, const int* in_sizes, int n_in,
                              void* d_out, int out_size) {
    const float* x       = (const float*)d_in[0];
    const float* norm_w  = (const float*)d_in[1];
    const float* norm_b  = (const float*)d_in[2];
    const float* fus_w1  = (const float*)d_in[21];
    const float* fus_b1  = (const float*)d_in[22];
    const float* fus_w2  = (const float*)d_in[23];
    const float* fus_b2  = (const float*)d_in[24];
    float* out = (float*)d_out;

    // branch inputs: [3..11] cw, [12..20] ccw
    const float* in_w [2] = {(const float*)d_in[3],  (const float*)d_in[12]};
    const float* cv_w [2] = {(const float*)d_in[4],  (const float*)d_in[13]};
    const float* cv_b [2] = {(const float*)d_in[5],  (const float*)d_in[14]};
    const float* xp_w [2] = {(const float*)d_in[6],  (const float*)d_in[15]};
    const float* dtp_w[2] = {(const float*)d_in[7],  (const float*)d_in[16]};
    const float* dtp_b[2] = {(const float*)d_in[8],  (const float*)d_in[17]};
    const float* A_log[2] = {(const float*)d_in[9],  (const float*)d_in[18]};
    const float* Dd   [2] = {(const float*)d_in[10], (const float*)d_in[19]};
    const float* out_w[2] = {(const float*)d_in[11], (const float*)d_in[20]};

    __nv_bfloat16* xn16 = sym<__nv_bfloat16>(g_xn16);
    __nv_bfloat16* fused16 = sym<__nv_bfloat16>(g_fused16);
    __nv_bfloat16* h16 = sym<__nv_bfloat16>(g_h16);
    float* xzp   = sym<float>(g_xz);
    float* dblp  = sym<float>(g_dbl);
    float* dtp   = sym<float>(g_dt);
    __nv_bfloat16* uc16p  = sym<__nv_bfloat16>(g_uc16);
    __nv_bfloat16* dbl16p = sym<__nv_bfloat16>(g_dbl16);
    __nv_bfloat16* y16p   = sym<__nv_bfloat16>(g_y16);
    __nv_bfloat16* inwt  = sym<__nv_bfloat16>(g_inwt);
    __nv_bfloat16* xpt   = sym<__nv_bfloat16>(g_xpt);
    __nv_bfloat16* dtpt  = sym<__nv_bfloat16>(g_dtpt);
    __nv_bfloat16* outwt = sym<__nv_bfloat16>(g_outwt);
    __nv_bfloat16* fw1t  = sym<__nv_bfloat16>(g_fw1t);
    __nv_bfloat16* fw2t  = sym<__nv_bfloat16>(g_fw2t);
    int* idx_cw  = sym<int>(g_idx_cw);
    int* idx_ccw = sym<int>(g_idx_ccw);
    const int* idx[2] = {idx_cw, idx_ccw};

    spiral_idx_kernel<<<1, LL>>>(idx_cw, idx_ccw);

    // weight transpose+convert (10 matrices, one launch)
    WAll wa;
    wa.w[0] = {in_w[0],  inwt,                 CC, 2*CC};
    wa.w[1] = {in_w[1],  inwt + 2*CC*CC,       CC, 2*CC};
    wa.w[2] = {xp_w[0],  xpt,                  CC, DBLC};
    wa.w[3] = {xp_w[1],  xpt + DBLC*CC,        CC, DBLC};
    wa.w[4] = {dtp_w[0], dtpt,                 DR, CC};
    wa.w[5] = {dtp_w[1], dtpt + CC*DR,         DR, CC};
    wa.w[6] = {out_w[0], outwt,                CC, CC};
    wa.w[7] = {out_w[1], outwt + CC*CC,        CC, CC};
    wa.w[8] = {fus_w1,   fw1t,                 2*CC, CC};
    wa.w[9] = {fus_w2,   fw2t,                 CC, CC};
    wt_kernel<<<dim3(48, 48, 10), dim3(32, 8)>>>(wa);

    layernorm_kernel<<<MTOT, 256>>>(x, norm_w, norm_b);

    dim3 thr(256);
    BrArgs a0, a1;
    // in_proj: xn16 @ inwt -> xz (fp32), gather perm
    a0 = {xn16, inwt,          nullptr, xzp,                 nullptr, idx[0], nullptr, 0};
    a1 = {xn16, inwt + 2*CC*CC, nullptr, xzp + MTOT*2*CC,    nullptr, idx[1], nullptr, 0};
    bf16gemm_kernel<<<dim3(12, 32, 2), thr>>>(a0, a1, CC, 2*CC, 2*CC, CC, 0, nullptr);

    conv_silu_kernel<<<dim3((MTOT*CC + 255)/256, 2), thr>>>(cv_w[0], cv_b[0], cv_w[1], cv_b[1]);

    // xproj: uc16 @ xpt -> dbl (fp32 + bf16)
    a0 = {uc16p,           xpt,           nullptr, dblp,              dbl16p,              nullptr, nullptr, 0};
    a1 = {uc16p + MTOT*CC, xpt + DBLC*CC, nullptr, dblp + MTOT*DBLC,  dbl16p + MTOT*DBLC,  nullptr, nullptr, 0};
    bf16gemm_kernel<<<dim3(1, 32, 2), thr>>>(a0, a1, CC, DBLC, DBLC, CC, 0, nullptr);

    // dt proj + softplus: dbl16[:, :48] @ dtpt -> dt (fp32)
    a0 = {dbl16p,             dtpt,         dtp_b[0], dtp,            nullptr, nullptr, nullptr, 0};
    a1 = {dbl16p + MTOT*DBLC, dtpt + CC*DR, dtp_b[1], dtp + MTOT*CC,  nullptr, nullptr, nullptr, 0};
    bf16gemm_kernel<<<dim3(6, 32, 2), thr>>>(a0, a1, DBLC, CC, CC, DR, 2, nullptr);

    scan_kernel<<<dim3((BB*CC)/8, 2), 128>>>(A_log[0], Dd[0], A_log[1], Dd[1]);

    // out proj with spiral scatter into fused16 concat buffer
    a0 = {y16p,           outwt,         nullptr, nullptr, fused16, nullptr, idx[0], 0};
    a1 = {y16p + MTOT*CC, outwt + CC*CC, nullptr, nullptr, fused16, nullptr, idx[1], CC};
    bf16gemm_kernel<<<dim3(6, 32, 2), thr>>>(a0, a1, CC, 2*CC, CC, CC, 0, nullptr);

    // fus1: fused16 @ fw1t + b1, GELU -> h16
    a0 = {fused16, fw1t, fus_b1, nullptr, h16, nullptr, nullptr, 0};
    bf16gemm_kernel<<<dim3(6, 32, 1), thr>>>(a0, a0, 2*CC, CC, CC, 2*CC, 1, nullptr);

    // fus2: h16 @ fw2t + b2 + residual x -> out (fp32)
    a0 = {h16, fw2t, fus_b2, out, nullptr, nullptr, nullptr, 0};
    bf16gemm_kernel<<<dim3(6, 32, 1), thr>>>(a0, a0, CC, CC, CC, CC, 0, x);
}

// round 9
// speedup vs baseline: 3.3915x; 1.2922x over previous
#include <cuda_runtime.h>
#include <cuda_bf16.h>
#include <cstdint>

// Problem constants (fixed by the dataset)
#define BB 4
#define LL 1024
#define HH 32
#define WW 32
#define CC 768
#define NN 16
#define DR 48
#define KK 4
#define MTOT (BB*LL)          // 4096
#define DBLC (DR + 2*NN)      // 80

// ---------------- scratch (no allocations allowed) ----------------
__device__ __nv_bfloat16 g_xn16[MTOT*CC];
__device__ float         g_xz  [2][MTOT*2*CC];
__device__ float         g_uc  [2][MTOT*CC];
__device__ __nv_bfloat16 g_uc16[2][MTOT*CC];
__device__ float         g_dbl [2][MTOT*DBLC];
__device__ __nv_bfloat16 g_dbl16[2][MTOT*DBLC];
__device__ float         g_dt  [2][MTOT*CC];
__device__ __nv_bfloat16 g_y16 [2][MTOT*CC];
__device__ __nv_bfloat16 g_fused16[MTOT*2*CC];
__device__ __nv_bfloat16 g_h16 [MTOT*CC];
__device__ int g_idx_cw [LL];
__device__ int g_idx_ccw[LL];
// bf16 transposed weights Wt[n][k]
__device__ __nv_bfloat16 g_inwt [2][2*CC*CC];
__device__ __nv_bfloat16 g_xpt  [2][DBLC*CC];
__device__ __nv_bfloat16 g_dtpt [2][CC*DR];
__device__ __nv_bfloat16 g_outwt[2][CC*CC];
__device__ __nv_bfloat16 g_fw1t [CC*2*CC];
__device__ __nv_bfloat16 g_fw2t [CC*CC];

// ---------------- spiral index generation ----------------
__global__ void spiral_idx_kernel(int* idx_cw, int* idx_ccw) {
    int cell = threadIdx.x;
    int i = cell / WW, j = cell % WW;
    int r = min(min(i, j), min(HH - 1 - i, WW - 1 - j));
    int h = HH - 2 * r, w = WW - 2 * r;
    int prior = HH * WW - h * w;
    int pos;
    if (i == r)                pos = j - r;
    else if (j == WW - 1 - r)  pos = (w - 1) + (i - r);
    else if (i == HH - 1 - r)  pos = (w - 1) + (h - 1) + (WW - 1 - r - j);
    else                       pos = 2*(w - 1) + (h - 1) + (HH - 1 - r - i);
    idx_cw[prior + pos] = cell;
    if (i == r)                pos = (WW - 1 - r) - j;
    else if (j == r)           pos = (w - 1) + (i - r);
    else if (i == HH - 1 - r)  pos = (w - 1) + (h - 1) + (j - r);
    else                       pos = 2*(w - 1) + (h - 1) + (HH - 1 - r - i);
    idx_ccw[prior + pos] = cell;
}

// ---------------- weight transpose+convert: in[K][N] f32 -> out[N][K] bf16 ----------------
struct WDesc { const float* in; __nv_bfloat16* out; int K; int N; };
struct WAll { WDesc w[10]; };
__global__ void wt_kernel(WAll all) {
    WDesc d = all.w[blockIdx.z];
    int n0 = blockIdx.x * 32, k0 = blockIdx.y * 32;
    if (n0 >= d.N || k0 >= d.K) return;
    __shared__ float t[32][33];
    int tx = threadIdx.x, ty = threadIdx.y;          // 32 x 8
#pragma unroll
    for (int i = 0; i < 32; i += 8) {
        int k = k0 + ty + i, n = n0 + tx;
        t[ty + i][tx] = (k < d.K && n < d.N) ? d.in[(size_t)k * d.N + n] : 0.f;
    }
    __syncthreads();
#pragma unroll
    for (int i = 0; i < 32; i += 8) {
        int n = n0 + ty + i, k = k0 + tx;
        if (n < d.N && k < d.K) d.out[(size_t)n * d.K + k] = __float2bfloat16(t[tx][ty + i]);
    }
}

// ---------------- layernorm -> bf16 ----------------
__global__ void layernorm_kernel(const float* __restrict__ x,
                                 const float* __restrict__ w,
                                 const float* __restrict__ b) {
    int row = blockIdx.x;
    const float* xr = x + (size_t)row * CC;
    float s = 0.f, s2 = 0.f;
    for (int c = threadIdx.x; c < CC; c += 256) {
        float v = xr[c];
        s += v; s2 += v * v;
    }
    __shared__ float sh_s[8], sh_s2[8];
    for (int o = 16; o > 0; o >>= 1) {
        s  += __shfl_xor_sync(0xffffffffu, s,  o);
        s2 += __shfl_xor_sync(0xffffffffu, s2, o);
    }
    int warp = threadIdx.x >> 5, lane = threadIdx.x & 31;
    if (lane == 0) { sh_s[warp] = s; sh_s2[warp] = s2; }
    __syncthreads();
    if (warp == 0) {
        s  = (lane < 8) ? sh_s[lane]  : 0.f;
        s2 = (lane < 8) ? sh_s2[lane] : 0.f;
        for (int o = 4; o > 0; o >>= 1) {
            s  += __shfl_xor_sync(0xffffffffu, s,  o);
            s2 += __shfl_xor_sync(0xffffffffu, s2, o);
        }
        if (lane == 0) { sh_s[0] = s; sh_s2[0] = s2; }
    }
    __syncthreads();
    float mu  = sh_s[0] * (1.f / CC);
    float var = sh_s2[0] * (1.f / CC) - mu * mu;
    float inv = rsqrtf(var + 1e-6f);
    for (int c = threadIdx.x; c < CC; c += 256)
        g_xn16[(size_t)row * CC + c] = __float2bfloat16((xr[c] - mu) * inv * w[c] + b[c]);
}

// ---------------- bf16 tensor-core GEMM, 3-stage cp.async pipeline ----------------
// BM=BN=128, BK=32, 256 threads, warp grid 2x4, warp tile 64x32, m16n8k16 bf16
#define APk 40                 // smem pitch in bf16 elems (80 B) — ldmatrix conflict-free
#define STGE (128*APk)         // elems per stage per matrix (5120)
#define NSTG 3
#define GEMM_SMEM (NSTG*2*STGE*2)   // bytes = 61440

struct BrArgs {
    const __nv_bfloat16* A;
    const __nv_bfloat16* Wt;       // [n][k]
    const float* bias;
    float* out32;
    __nv_bfloat16* out16;
    const int* a_perm;
    const int* o_perm;
    int o_coloff;
};

__device__ __forceinline__ void cp16(uint32_t dst, const void* src, int sz) {
    asm volatile("cp.async.cg.shared.global [%0], [%1], 16, %2;\n"
                 :: "r"(dst), "l"(src), "r"(sz));
}
__device__ __forceinline__ void ldsm4(uint32_t addr, uint32_t& r0, uint32_t& r1,
                                      uint32_t& r2, uint32_t& r3) {
    asm volatile("ldmatrix.sync.aligned.m8n8.x4.shared.b16 {%0,%1,%2,%3}, [%4];"
                 : "=r"(r0), "=r"(r1), "=r"(r2), "=r"(r3) : "r"(addr));
}

__global__ __launch_bounds__(256, 3)
void bf16gemm_kernel(BrArgs P0, BrArgs P1, int lda, int ldo, int Nn, int Kk,
                     int act, const float* __restrict__ resid) {
    BrArgs P = (blockIdx.z == 0) ? P0 : P1;
    extern __shared__ __nv_bfloat16 smem[];  // [NSTG stages: A(5120) then B(5120)]
    int tid = threadIdx.x;
    int row0 = blockIdx.y * 128, col0 = blockIdx.x * 128;
    int warp = tid >> 5, lane = tid & 31;
    int wm = warp >> 2, wn = warp & 3;
    int g = lane >> 2, t4 = lane & 3;

    // ---- loader mapping: each thread owns one row-slot, two 8-elem chunks
    int lrow = tid >> 1;                 // 0..127
    int kc0 = (tid & 1) * 16, kc1 = kc0 + 8;
    int garow = row0 + lrow;
    if (P.a_perm) garow = (garow & ~(LL - 1)) + P.a_perm[garow & (LL - 1)];
    const __nv_bfloat16* abase = P.A + (size_t)garow * lda;
    int gn = col0 + lrow;
    const __nv_bfloat16* bbase = P.Wt + (size_t)(gn < Nn ? gn : 0) * Kk;
    bool bok = (gn < Nn);

    uint32_t sbase = (uint32_t)__cvta_generic_to_shared(smem);
    uint32_t aoff0 = (lrow * APk + kc0) * 2;
    uint32_t aoff1 = (lrow * APk + kc1) * 2;

    // ---- ldmatrix lane offsets (element offsets within a stage)
    uint32_t a_off[4], b_off[2];
    {
        int arl = lane & 15, akhi = (lane >> 4) << 3;
#pragma unroll
        for (int mi = 0; mi < 4; mi++)
            a_off[mi] = ((wm * 64 + mi * 16 + arl) * APk + akhi) * 2;
        int bnr = ((lane >> 4) << 3) + (lane & 7);
        int bkhi = ((lane >> 3) & 1) << 3;
#pragma unroll
        for (int np = 0; np < 2; np++)
            b_off[np] = ((wn * 32 + np * 16 + bnr) * APk + bkhi) * 2;
    }

    float acc[4][4][4];
#pragma unroll
    for (int i = 0; i < 4; i++)
#pragma unroll
        for (int j = 0; j < 4; j++)
#pragma unroll
            for (int q = 0; q < 4; q++) acc[i][j][q] = 0.f;

    int ntiles = (Kk + 31) >> 5;

    auto issue = [&](int t) {
        if (t < ntiles) {
            int s = t % NSTG;
            uint32_t sa = sbase + s * (2 * STGE) * 2;
            uint32_t sb = sa + STGE * 2;
            int k0 = t * 32;
            int s0 = (k0 + kc0 < Kk) ? 16 : 0, s1 = (k0 + kc1 < Kk) ? 16 : 0;
            cp16(sa + aoff0, abase + k0 + kc0, s0);
            cp16(sa + aoff1, abase + k0 + kc1, s1);
            cp16(sb + aoff0, bbase + k0 + kc0, bok ? s0 : 0);
            cp16(sb + aoff1, bbase + k0 + kc1, bok ? s1 : 0);
        }
        asm volatile("cp.async.commit_group;\n");
    };

    issue(0); issue(1); issue(2);

    for (int t = 0; t < ntiles; t++) {
        asm volatile("cp.async.wait_group 2;\n");
        __syncthreads();
        int s = t % NSTG;
        uint32_t abuf = sbase + s * (2 * STGE) * 2;
        uint32_t bbuf = abuf + STGE * 2;
#pragma unroll
        for (int kk = 0; kk < 32; kk += 16) {
            uint32_t af[4][4], bf[4][2];
#pragma unroll
            for (int mi = 0; mi < 4; mi++)
                ldsm4(abuf + kk * 2 + a_off[mi],
                      af[mi][0], af[mi][1], af[mi][2], af[mi][3]);
#pragma unroll
            for (int np = 0; np < 2; np++)
                ldsm4(bbuf + kk * 2 + b_off[np],
                      bf[2*np][0], bf[2*np][1], bf[2*np+1][0], bf[2*np+1][1]);
#pragma unroll
            for (int mi = 0; mi < 4; mi++)
#pragma unroll
                for (int ni = 0; ni < 4; ni++)
                    asm volatile(
                        "mma.sync.aligned.m16n8k16.row.col.f32.bf16.bf16.f32 "
                        "{%0,%1,%2,%3}, {%4,%5,%6,%7}, {%8,%9}, {%0,%1,%2,%3};\n"
                        : "+f"(acc[mi][ni][0]), "+f"(acc[mi][ni][1]),
                          "+f"(acc[mi][ni][2]), "+f"(acc[mi][ni][3])
                        : "r"(af[mi][0]), "r"(af[mi][1]), "r"(af[mi][2]), "r"(af[mi][3]),
                          "r"(bf[ni][0]), "r"(bf[ni][1]));
        }
        __syncthreads();
        issue(t + 3);
    }

    // ---- epilogue
#pragma unroll
    for (int mi = 0; mi < 4; mi++) {
#pragma unroll
        for (int half = 0; half < 2; half++) {
            int grow = row0 + wm * 64 + mi * 16 + g + half * 8;
            int orow = grow;
            if (P.o_perm) orow = (grow & ~(LL - 1)) + P.o_perm[grow & (LL - 1)];
#pragma unroll
            for (int ni = 0; ni < 4; ni++) {
                int gc = col0 + wn * 32 + ni * 8 + 2 * t4;
                if (gc >= Nn) continue;
                float v0 = acc[mi][ni][half * 2 + 0];
                float v1 = acc[mi][ni][half * 2 + 1];
                if (P.bias) { v0 += P.bias[gc]; v1 += P.bias[gc + 1]; }
                if (act == 1) {                       // exact GELU
                    v0 = 0.5f * v0 * (1.f + erff(v0 * 0.70710678118654752f));
                    v1 = 0.5f * v1 * (1.f + erff(v1 * 0.70710678118654752f));
                } else if (act == 2) {                // softplus
                    v0 = (v0 > 20.f) ? v0 : log1pf(expf(v0));
                    v1 = (v1 > 20.f) ? v1 : log1pf(expf(v1));
                }
                if (resid) {
                    v0 += resid[(size_t)grow * Nn + gc];
                    v1 += resid[(size_t)grow * Nn + gc + 1];
                }
                size_t oidx = (size_t)orow * ldo + P.o_coloff + gc;
                if (P.out32) *(float2*)(P.out32 + oidx) = make_float2(v0, v1);
                if (P.out16) *(__nv_bfloat162*)(P.out16 + oidx) = __floats2bfloat162_rn(v0, v1);
            }
        }
    }
}

// ---------------- causal depthwise conv (K=4) + SiLU, dual-branch ----------------
__global__ void conv_silu_kernel(const float* __restrict__ cw0, const float* __restrict__ cb0,
                                 const float* __restrict__ cw1, const float* __restrict__ cb1) {
    int br = blockIdx.y;
    const float* xz = g_xz[br];
    const float* cw = br ? cw1 : cw0;
    const float* cb = br ? cb1 : cb0;
    int t = blockIdx.x * blockDim.x + threadIdx.x;
    if (t >= MTOT * CC) return;
    int d = t % CC;
    int m = t / CC;
    int l = m & (LL - 1);
    float acc = cb[d];
#pragma unroll
    for (int k = 0; k < KK; k++) {
        int ls = l - (KK - 1) + k;
        if (ls >= 0) acc = fmaf(cw[d * KK + k],
                                xz[(size_t)(m - (KK - 1) + k) * (2 * CC) + d], acc);
    }
    float s = 1.f / (1.f + __expf(-acc));
    float v = acc * s;
    g_uc[br][t] = v;
    g_uc16[br][t] = __float2bfloat16(v);
}

// ---------------- selective scan, dual-branch, software-pipelined ----------------
__global__ __launch_bounds__(128)
void scan_kernel(const float* __restrict__ A0, const float* __restrict__ D0,
                 const float* __restrict__ A1, const float* __restrict__ D1) {
    int br = blockIdx.y;
    const float* __restrict__ dt  = g_dt[br];
    const float* __restrict__ dbl = g_dbl[br];
    const float* __restrict__ uc  = g_uc[br];
    const float* __restrict__ xz  = g_xz[br];
    const float* Alog = br ? A1 : A0;
    const float* Dp   = br ? D1 : D0;
    int gidx = blockIdx.x * 8 + (threadIdx.x >> 4);   // 0..3071
    int n = threadIdx.x & 15;
    int b = gidx / CC, d = gidx % CC;
    float a  = -expf(Alog[d * NN + n]);
    float Dv = Dp[d];
    size_t base = (size_t)b * LL;
    const float* dtP  = dt  + base * CC + d;
    const float* ucP  = uc  + base * CC + d;
    const float* dblP = dbl + base * DBLC + DR + n;
    const float* xzP  = xz  + base * (2 * CC) + CC + d;
    __nv_bfloat16* yP = g_y16[br] + base * CC + d;

    float h = 0.f;
    float dtv = __ldg(dtP), uv = __ldg(ucP);
    float bv = __ldg(dblP), cv = __ldg(dblP + NN);
#pragma unroll 2
    for (int l = 0; l < LL; l++) {
        // prefetch next timestep before the serial chain
        float ndt = 0.f, nuv = 0.f, nbv = 0.f, ncv = 0.f;
        if (l + 1 < LL) {
            ndt = __ldg(dtP + (size_t)(l + 1) * CC);
            nuv = __ldg(ucP + (size_t)(l + 1) * CC);
            nbv = __ldg(dblP + (size_t)(l + 1) * DBLC);
            ncv = __ldg(dblP + (size_t)(l + 1) * DBLC + NN);
        }
        float dA = __expf(dtv * a);
        h = fmaf(h, dA, dtv * bv * uv);
        float yp = h * cv;
        yp += __shfl_xor_sync(0xffffffffu, yp, 1);
        yp += __shfl_xor_sync(0xffffffffu, yp, 2);
        yp += __shfl_xor_sync(0xffffffffu, yp, 4);
        yp += __shfl_xor_sync(0xffffffffu, yp, 8);
        if (n == 0) {
            float zv = __ldg(xzP + (size_t)l * 2 * CC);
            float sz = zv / (1.f + __expf(-zv));
            yP[(size_t)l * CC] = __float2bfloat16((yp + Dv * uv) * sz);
        }
        dtv = ndt; uv = nuv; bv = nbv; cv = ncv;
    }
}

// ---------------- host side ----------------
template <typename T> static T* sym(const void* s) {
    void* p = nullptr; cudaGetSymbolAddress(&p, s); return (T*)p;
}

extern "C" void kernel_launch(void* const* d_in, const int* in_sizes, int n_in,
                              void* d_out, int out_size) {
    const float* x       = (const float*)d_in[0];
    const float* norm_w  = (const float*)d_in[1];
    const float* norm_b  = (const float*)d_in[2];
    const float* fus_w1  = (const float*)d_in[21];
    const float* fus_b1  = (const float*)d_in[22];
    const float* fus_w2  = (const float*)d_in[23];
    const float* fus_b2  = (const float*)d_in[24];
    float* out = (float*)d_out;

    const float* in_w [2] = {(const float*)d_in[3],  (const float*)d_in[12]};
    const float* cv_w [2] = {(const float*)d_in[4],  (const float*)d_in[13]};
    const float* cv_b [2] = {(const float*)d_in[5],  (const float*)d_in[14]};
    const float* xp_w [2] = {(const float*)d_in[6],  (const float*)d_in[15]};
    const float* dtp_w[2] = {(const float*)d_in[7],  (const float*)d_in[16]};
    const float* dtp_b[2] = {(const float*)d_in[8],  (const float*)d_in[17]};
    const float* A_log[2] = {(const float*)d_in[9],  (const float*)d_in[18]};
    const float* Dd   [2] = {(const float*)d_in[10], (const float*)d_in[19]};
    const float* out_w[2] = {(const float*)d_in[11], (const float*)d_in[20]};

    __nv_bfloat16* xn16 = sym<__nv_bfloat16>(g_xn16);
    __nv_bfloat16* fused16 = sym<__nv_bfloat16>(g_fused16);
    __nv_bfloat16* h16 = sym<__nv_bfloat16>(g_h16);
    float* xzp   = sym<float>(g_xz);
    float* dblp  = sym<float>(g_dbl);
    float* dtp   = sym<float>(g_dt);
    __nv_bfloat16* uc16p  = sym<__nv_bfloat16>(g_uc16);
    __nv_bfloat16* dbl16p = sym<__nv_bfloat16>(g_dbl16);
    __nv_bfloat16* y16p   = sym<__nv_bfloat16>(g_y16);
    __nv_bfloat16* inwt  = sym<__nv_bfloat16>(g_inwt);
    __nv_bfloat16* xpt   = sym<__nv_bfloat16>(g_xpt);
    __nv_bfloat16* dtpt  = sym<__nv_bfloat16>(g_dtpt);
    __nv_bfloat16* outwt = sym<__nv_bfloat16>(g_outwt);
    __nv_bfloat16* fw1t  = sym<__nv_bfloat16>(g_fw1t);
    __nv_bfloat16* fw2t  = sym<__nv_bfloat16>(g_fw2t);
    int* idx_cw  = sym<int>(g_idx_cw);
    int* idx_ccw = sym<int>(g_idx_ccw);
    const int* idx[2] = {idx_cw, idx_ccw};

    cudaFuncSetAttribute(bf16gemm_kernel,
                         cudaFuncAttributeMaxDynamicSharedMemorySize, GEMM_SMEM);

    spiral_idx_kernel<<<1, LL>>>(idx_cw, idx_ccw);

    WAll wa;
    wa.w[0] = {in_w[0],  inwt,                 CC, 2*CC};
    wa.w[1] = {in_w[1],  inwt + 2*CC*CC,       CC, 2*CC};
    wa.w[2] = {xp_w[0],  xpt,                  CC, DBLC};
    wa.w[3] = {xp_w[1],  xpt + DBLC*CC,        CC, DBLC};
    wa.w[4] = {dtp_w[0], dtpt,                 DR, CC};
    wa.w[5] = {dtp_w[1], dtpt + CC*DR,         DR, CC};
    wa.w[6] = {out_w[0], outwt,                CC, CC};
    wa.w[7] = {out_w[1], outwt + CC*CC,        CC, CC};
    wa.w[8] = {fus_w1,   fw1t,                 2*CC, CC};
    wa.w[9] = {fus_w2,   fw2t,                 CC, CC};
    wt_kernel<<<dim3(48, 48, 10), dim3(32, 8)>>>(wa);

    layernorm_kernel<<<MTOT, 256>>>(x, norm_w, norm_b);

    BrArgs a0, a1;
    // in_proj: xn16 @ inwt -> xz (fp32), spiral gather
    a0 = {xn16, inwt,           nullptr, xzp,              nullptr, idx[0], nullptr, 0};
    a1 = {xn16, inwt + 2*CC*CC, nullptr, xzp + MTOT*2*CC,  nullptr, idx[1], nullptr, 0};
    bf16gemm_kernel<<<dim3(12, 32, 2), 256, GEMM_SMEM>>>(a0, a1, CC, 2*CC, 2*CC, CC, 0, nullptr);

    conv_silu_kernel<<<dim3((MTOT*CC + 255)/256, 2), 256>>>(cv_w[0], cv_b[0], cv_w[1], cv_b[1]);

    // xproj: uc16 @ xpt -> dbl (fp32 + bf16)
    a0 = {uc16p,           xpt,           nullptr, dblp,             dbl16p,             nullptr, nullptr, 0};
    a1 = {uc16p + MTOT*CC, xpt + DBLC*CC, nullptr, dblp + MTOT*DBLC, dbl16p + MTOT*DBLC, nullptr, nullptr, 0};
    bf16gemm_kernel<<<dim3(1, 32, 2), 256, GEMM_SMEM>>>(a0, a1, CC, DBLC, DBLC, CC, 0, nullptr);

    // dt proj + softplus: dbl16[:, :48] @ dtpt -> dt (fp32)
    a0 = {dbl16p,             dtpt,         dtp_b[0], dtp,           nullptr, nullptr, nullptr, 0};
    a1 = {dbl16p + MTOT*DBLC, dtpt + CC*DR, dtp_b[1], dtp + MTOT*CC, nullptr, nullptr, nullptr, 0};
    bf16gemm_kernel<<<dim3(6, 32, 2), 256, GEMM_SMEM>>>(a0, a1, DBLC, CC, CC, DR, 2, nullptr);

    scan_kernel<<<dim3((BB*CC)/8, 2), 128>>>(A_log[0], Dd[0], A_log[1], Dd[1]);

    // out proj with spiral scatter into fused16 concat buffer
    a0 = {y16p,           outwt,         nullptr, nullptr, fused16, nullptr, idx[0], 0};
    a1 = {y16p + MTOT*CC, outwt + CC*CC, nullptr, nullptr, fused16, nullptr, idx[1], CC};
    bf16gemm_kernel<<<dim3(6, 32, 2), 256, GEMM_SMEM>>>(a0, a1, CC, 2*CC, CC, CC, 0, nullptr);

    // fus1: fused16 @ fw1t + b1, GELU -> h16
    a0 = {fused16, fw1t, fus_b1, nullptr, h16, nullptr, nullptr, 0};
    bf16gemm_kernel<<<dim3(6, 32, 1), 256, GEMM_SMEM>>>(a0, a0, 2*CC, CC, CC, 2*CC, 1, nullptr);

    // fus2: h16 @ fw2t + b2 + residual x -> out (fp32)
    a0 = {h16, fw2t, fus_b2, out, nullptr, nullptr, nullptr, 0};
    bf16gemm_kernel<<<dim3(6, 32, 1), 256, GEMM_SMEM>>>(a0, a0, CC, CC, CC, CC, 0, x);
}

// round 11
// speedup vs baseline: 5.7134x; 1.6846x over previous
#include <cuda_runtime.h>
#include <cuda_bf16.h>
#include <cstdint>

// Problem constants (fixed by the dataset)
#define BB 4
#define LL 1024
#define HH 32
#define WW 32
#define CC 768
#define NN 16
#define DR 48
#define KK 4
#define MTOT (BB*LL)          // 4096
#define DBLC (DR + 2*NN)      // 80

// ---------------- scratch (no allocations allowed) ----------------
__device__ __nv_bfloat16 g_xn16[MTOT*CC];
__device__ float         g_xz  [2][MTOT*2*CC];
__device__ float         g_uc  [2][MTOT*CC];
__device__ __nv_bfloat16 g_uc16[2][MTOT*CC];
__device__ float         g_dbl [2][MTOT*DBLC];
__device__ __nv_bfloat16 g_dbl16[2][MTOT*DBLC];
__device__ float         g_dt  [2][MTOT*CC];
__device__ __nv_bfloat16 g_y16 [2][MTOT*CC];
__device__ __nv_bfloat16 g_fused16[MTOT*2*CC];
__device__ __nv_bfloat16 g_h16 [MTOT*CC];
__device__ int g_idx_cw [LL];
__device__ int g_idx_ccw[LL];
// bf16 transposed weights Wt[n][k]
__device__ __nv_bfloat16 g_inwt [2][2*CC*CC];
__device__ __nv_bfloat16 g_xpt  [2][DBLC*CC];
__device__ __nv_bfloat16 g_dtpt [2][CC*DR];
__device__ __nv_bfloat16 g_outwt[2][CC*CC];
__device__ __nv_bfloat16 g_fw1t [CC*2*CC];
__device__ __nv_bfloat16 g_fw2t [CC*CC];

// ---------------- spiral index generation ----------------
__global__ void spiral_idx_kernel(int* idx_cw, int* idx_ccw) {
    int cell = threadIdx.x;
    int i = cell / WW, j = cell % WW;
    int r = min(min(i, j), min(HH - 1 - i, WW - 1 - j));
    int h = HH - 2 * r, w = WW - 2 * r;
    int prior = HH * WW - h * w;
    int pos;
    if (i == r)                pos = j - r;
    else if (j == WW - 1 - r)  pos = (w - 1) + (i - r);
    else if (i == HH - 1 - r)  pos = (w - 1) + (h - 1) + (WW - 1 - r - j);
    else                       pos = 2*(w - 1) + (h - 1) + (HH - 1 - r - i);
    idx_cw[prior + pos] = cell;
    if (i == r)                pos = (WW - 1 - r) - j;
    else if (j == r)           pos = (w - 1) + (i - r);
    else if (i == HH - 1 - r)  pos = (w - 1) + (h - 1) + (j - r);
    else                       pos = 2*(w - 1) + (h - 1) + (HH - 1 - r - i);
    idx_ccw[prior + pos] = cell;
}

// ---------------- weight transpose+convert: in[K][N] f32 -> out[N][K] bf16 ----------------
struct WDesc { const float* in; __nv_bfloat16* out; int K; int N; };
struct WAll { WDesc w[10]; };
__global__ void wt_kernel(WAll all) {
    WDesc d = all.w[blockIdx.z];
    int n0 = blockIdx.x * 32, k0 = blockIdx.y * 32;
    if (n0 >= d.N || k0 >= d.K) return;
    __shared__ float t[32][33];
    int tx = threadIdx.x, ty = threadIdx.y;          // 32 x 8
#pragma unroll
    for (int i = 0; i < 32; i += 8) {
        int k = k0 + ty + i, n = n0 + tx;
        t[ty + i][tx] = (k < d.K && n < d.N) ? d.in[(size_t)k * d.N + n] : 0.f;
    }
    __syncthreads();
#pragma unroll
    for (int i = 0; i < 32; i += 8) {
        int n = n0 + ty + i, k = k0 + tx;
        if (n < d.N && k < d.K) d.out[(size_t)n * d.K + k] = __float2bfloat16(t[tx][ty + i]);
    }
}

// ---------------- layernorm -> bf16 ----------------
__global__ void layernorm_kernel(const float* __restrict__ x,
                                 const float* __restrict__ w,
                                 const float* __restrict__ b) {
    int row = blockIdx.x;
    const float* xr = x + (size_t)row * CC;
    float s = 0.f, s2 = 0.f;
    for (int c = threadIdx.x; c < CC; c += 256) {
        float v = xr[c];
        s += v; s2 += v * v;
    }
    __shared__ float sh_s[8], sh_s2[8];
    for (int o = 16; o > 0; o >>= 1) {
        s  += __shfl_xor_sync(0xffffffffu, s,  o);
        s2 += __shfl_xor_sync(0xffffffffu, s2, o);
    }
    int warp = threadIdx.x >> 5, lane = threadIdx.x & 31;
    if (lane == 0) { sh_s[warp] = s; sh_s2[warp] = s2; }
    __syncthreads();
    if (warp == 0) {
        s  = (lane < 8) ? sh_s[lane]  : 0.f;
        s2 = (lane < 8) ? sh_s2[lane] : 0.f;
        for (int o = 4; o > 0; o >>= 1) {
            s  += __shfl_xor_sync(0xffffffffu, s,  o);
            s2 += __shfl_xor_sync(0xffffffffu, s2, o);
        }
        if (lane == 0) { sh_s[0] = s; sh_s2[0] = s2; }
    }
    __syncthreads();
    float mu  = sh_s[0] * (1.f / CC);
    float var = sh_s2[0] * (1.f / CC) - mu * mu;
    float inv = rsqrtf(var + 1e-6f);
    for (int c = threadIdx.x; c < CC; c += 256)
        g_xn16[(size_t)row * CC + c] = __float2bfloat16((xr[c] - mu) * inv * w[c] + b[c]);
}

// ---------------- bf16 tensor-core GEMM with fused epilogues (R6 measured-best) ----------
// BM=BN=128, BK=32, 256 threads, warp grid 2x4, warp tile 64x32, m16n8k16 bf16
#define APk 40                 // smem pitch in bf16 elems (80 B) — ldmatrix conflict-free
#define ABUFE (128*APk)        // elems per buffer

struct BrArgs {
    const __nv_bfloat16* A;
    const __nv_bfloat16* Wt;       // [n][k]
    const float* bias;
    float* out32;
    __nv_bfloat16* out16;
    const int* a_perm;
    const int* o_perm;
    int o_coloff;
};

__device__ __forceinline__ void cp16(uint32_t dst, const void* src, int sz) {
    asm volatile("cp.async.cg.shared.global [%0], [%1], 16, %2;\n"
                 :: "r"(dst), "l"(src), "r"(sz));
}
__device__ __forceinline__ void ldsm4(uint32_t addr, uint32_t& r0, uint32_t& r1,
                                      uint32_t& r2, uint32_t& r3) {
    asm volatile("ldmatrix.sync.aligned.m8n8.x4.shared.b16 {%0,%1,%2,%3}, [%4];"
                 : "=r"(r0), "=r"(r1), "=r"(r2), "=r"(r3) : "r"(addr));
}

__global__ __launch_bounds__(256)
void bf16gemm_kernel(BrArgs P0, BrArgs P1, int lda, int ldo, int Nn, int Kk,
                     int act, const float* __restrict__ resid) {
    BrArgs P = (blockIdx.z == 0) ? P0 : P1;
    __shared__ __nv_bfloat16 As[2 * ABUFE];
    __shared__ __nv_bfloat16 Bs[2 * ABUFE];
    int tid = threadIdx.x;
    int row0 = blockIdx.y * 128, col0 = blockIdx.x * 128;
    int warp = tid >> 5, lane = tid & 31;
    int wm = warp >> 2, wn = warp & 3;
    int g = lane >> 2, t4 = lane & 3;

    // ---- loader mapping: each thread owns one row-slot, two 8-elem chunks
    int lrow = tid >> 1;                 // 0..127
    int kc0 = (tid & 1) * 16, kc1 = kc0 + 8;
    int garow = row0 + lrow;
    if (P.a_perm) garow = (garow & ~(LL - 1)) + P.a_perm[garow & (LL - 1)];
    const __nv_bfloat16* abase = P.A + (size_t)garow * lda;
    int gn = col0 + lrow;
    const __nv_bfloat16* bbase = P.Wt + (size_t)(gn < Nn ? gn : 0) * Kk;
    bool bok = (gn < Nn);

    uint32_t asb = (uint32_t)__cvta_generic_to_shared(As);
    uint32_t bsb = (uint32_t)__cvta_generic_to_shared(Bs);
    uint32_t dA0 = asb + (lrow * APk + kc0) * 2;
    uint32_t dA1 = asb + (lrow * APk + kc1) * 2;
    uint32_t dB0 = bsb + (lrow * APk + kc0) * 2;
    uint32_t dB1 = bsb + (lrow * APk + kc1) * 2;

    // ---- ldmatrix lane offsets
    uint32_t a_off[4], b_off[2];
    {
        int arl = lane & 15, akhi = (lane >> 4) << 3;
#pragma unroll
        for (int mi = 0; mi < 4; mi++)
            a_off[mi] = ((wm * 64 + mi * 16 + arl) * APk + akhi) * 2;
        int bnr = ((lane >> 4) << 3) + (lane & 7);
        int bkhi = ((lane >> 3) & 1) << 3;
#pragma unroll
        for (int np = 0; np < 2; np++)
            b_off[np] = ((wn * 32 + np * 16 + bnr) * APk + bkhi) * 2;
    }

    float acc[4][4][4];
#pragma unroll
    for (int i = 0; i < 4; i++)
#pragma unroll
        for (int j = 0; j < 4; j++)
#pragma unroll
            for (int q = 0; q < 4; q++) acc[i][j][q] = 0.f;

    int ntiles = (Kk + 31) >> 5;
    // preload tile 0
    {
        int sA0 = (kc0 < Kk) ? 16 : 0, sA1 = (kc1 < Kk) ? 16 : 0;
        cp16(dA0, abase + kc0, sA0);
        cp16(dA1, abase + kc1, sA1);
        cp16(dB0, bbase + kc0, bok ? sA0 : 0);
        cp16(dB1, bbase + kc1, bok ? sA1 : 0);
        asm volatile("cp.async.commit_group;\n");
    }

    for (int t = 0; t < ntiles; t++) {
        int buf = t & 1;
        if (t + 1 < ntiles) {
            int nb = (t + 1) & 1, k0 = (t + 1) * 32;
            uint32_t bo = nb * ABUFE * 2;
            int s0 = (k0 + kc0 < Kk) ? 16 : 0, s1 = (k0 + kc1 < Kk) ? 16 : 0;
            cp16(dA0 + bo, abase + k0 + kc0, s0);
            cp16(dA1 + bo, abase + k0 + kc1, s1);
            cp16(dB0 + bo, bbase + k0 + kc0, bok ? s0 : 0);
            cp16(dB1 + bo, bbase + k0 + kc1, bok ? s1 : 0);
            asm volatile("cp.async.commit_group;\n");
            asm volatile("cp.async.wait_group 1;\n");
        } else {
            asm volatile("cp.async.wait_group 0;\n");
        }
        __syncthreads();
        uint32_t abuf = asb + buf * ABUFE * 2;
        uint32_t bbuf = bsb + buf * ABUFE * 2;
#pragma unroll
        for (int kk = 0; kk < 32; kk += 16) {
            uint32_t af[4][4], bf[4][2];
#pragma unroll
            for (int mi = 0; mi < 4; mi++)
                ldsm4(abuf + kk * 2 + a_off[mi],
                      af[mi][0], af[mi][1], af[mi][2], af[mi][3]);
#pragma unroll
            for (int np = 0; np < 2; np++)
                ldsm4(bbuf + kk * 2 + b_off[np],
                      bf[2*np][0], bf[2*np][1], bf[2*np+1][0], bf[2*np+1][1]);
#pragma unroll
            for (int mi = 0; mi < 4; mi++)
#pragma unroll
                for (int ni = 0; ni < 4; ni++)
                    asm volatile(
                        "mma.sync.aligned.m16n8k16.row.col.f32.bf16.bf16.f32 "
                        "{%0,%1,%2,%3}, {%4,%5,%6,%7}, {%8,%9}, {%0,%1,%2,%3};\n"
                        : "+f"(acc[mi][ni][0]), "+f"(acc[mi][ni][1]),
                          "+f"(acc[mi][ni][2]), "+f"(acc[mi][ni][3])
                        : "r"(af[mi][0]), "r"(af[mi][1]), "r"(af[mi][2]), "r"(af[mi][3]),
                          "r"(bf[ni][0]), "r"(bf[ni][1]));
        }
        __syncthreads();
    }

    // ---- epilogue
#pragma unroll
    for (int mi = 0; mi < 4; mi++) {
#pragma unroll
        for (int half = 0; half < 2; half++) {
            int grow = row0 + wm * 64 + mi * 16 + g + half * 8;
            int orow = grow;
            if (P.o_perm) orow = (grow & ~(LL - 1)) + P.o_perm[grow & (LL - 1)];
#pragma unroll
            for (int ni = 0; ni < 4; ni++) {
                int gc = col0 + wn * 32 + ni * 8 + 2 * t4;
                if (gc >= Nn) continue;
                float v0 = acc[mi][ni][half * 2 + 0];
                float v1 = acc[mi][ni][half * 2 + 1];
                if (P.bias) { v0 += P.bias[gc]; v1 += P.bias[gc + 1]; }
                if (act == 1) {                       // exact GELU
                    v0 = 0.5f * v0 * (1.f + erff(v0 * 0.70710678118654752f));
                    v1 = 0.5f * v1 * (1.f + erff(v1 * 0.70710678118654752f));
                } else if (act == 2) {                // softplus
                    v0 = (v0 > 20.f) ? v0 : log1pf(expf(v0));
                    v1 = (v1 > 20.f) ? v1 : log1pf(expf(v1));
                }
                if (resid) {
                    v0 += resid[(size_t)grow * Nn + gc];
                    v1 += resid[(size_t)grow * Nn + gc + 1];
                }
                size_t oidx = (size_t)orow * ldo + P.o_coloff + gc;
                if (P.out32) *(float2*)(P.out32 + oidx) = make_float2(v0, v1);
                if (P.out16) *(__nv_bfloat162*)(P.out16 + oidx) = __floats2bfloat162_rn(v0, v1);
            }
        }
    }
}

// ---------------- causal depthwise conv (K=4) + SiLU, dual-branch ----------------
__global__ void conv_silu_kernel(const float* __restrict__ cw0, const float* __restrict__ cb0,
                                 const float* __restrict__ cw1, const float* __restrict__ cb1) {
    int br = blockIdx.y;
    const float* xz = g_xz[br];
    const float* cw = br ? cw1 : cw0;
    const float* cb = br ? cb1 : cb0;
    int t = blockIdx.x * blockDim.x + threadIdx.x;
    if (t >= MTOT * CC) return;
    int d = t % CC;
    int m = t / CC;
    int l = m & (LL - 1);
    float acc = cb[d];
#pragma unroll
    for (int k = 0; k < KK; k++) {
        int ls = l - (KK - 1) + k;
        if (ls >= 0) acc = fmaf(cw[d * KK + k],
                                xz[(size_t)(m - (KK - 1) + k) * (2 * CC) + d], acc);
    }
    float s = 1.f / (1.f + __expf(-acc));
    float v = acc * s;
    g_uc[br][t] = v;
    g_uc16[br][t] = __float2bfloat16(v);
}

// ---------------- selective scan: smem-staged cp.async pipeline ----------------
// Block: 128 threads = 8 channels x 16 state lanes, one (branch, b, d0..d0+7).
// Chunk ST timesteps staged per buffer: [dt(8) | uc(8) | B(16) | C(16) | z(8)] = 56 floats/l.
#define ST 64
#define SROW 56
__global__ __launch_bounds__(128)
void scan_kernel(const float* __restrict__ A0, const float* __restrict__ D0,
                 const float* __restrict__ A1, const float* __restrict__ D1) {
    int br = blockIdx.y;
    int b  = blockIdx.x / (CC / 8);
    int d0 = (blockIdx.x % (CC / 8)) * 8;
    const float* __restrict__ dt  = g_dt[br];
    const float* __restrict__ dbl = g_dbl[br];
    const float* __restrict__ uc  = g_uc[br];
    const float* __restrict__ xz  = g_xz[br];
    const float* Alog = br ? A1 : A0;
    const float* Dp   = br ? D1 : D0;
    int tid = threadIdx.x;
    int ch = tid >> 4;            // 0..7
    int n  = tid & 15;
    int d  = d0 + ch;
    float a  = -expf(Alog[d * NN + n]);
    float Dv = Dp[d];
    size_t mbase = (size_t)b * LL;

    __shared__ float sbuf[2][ST * SROW];
    uint32_t sb = (uint32_t)__cvta_generic_to_shared(sbuf);

    const float* dtB = dt  + mbase * CC + d0;
    const float* ucB = uc  + mbase * CC + d0;
    const float* bcB = dbl + mbase * DBLC + DR;
    const float* zB  = xz  + mbase * 2 * CC + CC + d0;
    __nv_bfloat16* yB = g_y16[br] + mbase * CC + d;

    auto issue = [&](int c) {
        int l0 = c * ST;
        uint32_t dstb = sb + (uint32_t)(c & 1) * (ST * SROW * 4);
        // 14 x 16B pieces per timestep
        for (int j = tid; j < ST * 14; j += 128) {
            int ll = j / 14, piece = j % 14;
            int l = l0 + ll;
            uint32_t dst = dstb + (uint32_t)(ll * SROW + piece * 4) * 4;
            const float* src;
            if (piece < 2)       src = dtB + (size_t)l * CC   + piece * 4;
            else if (piece < 4)  src = ucB + (size_t)l * CC   + (piece - 2) * 4;
            else if (piece < 12) src = bcB + (size_t)l * DBLC + (piece - 4) * 4;
            else                 src = zB  + (size_t)l * 2*CC + (piece - 12) * 4;
            cp16(dst, src, 16);
        }
        asm volatile("cp.async.commit_group;\n");
    };

    issue(0);
    float h = 0.f;
    const int NCH = LL / ST;      // 16
    for (int c = 0; c < NCH; c++) {
        if (c + 1 < NCH) issue(c + 1);
        else asm volatile("cp.async.commit_group;\n");
        asm volatile("cp.async.wait_group 1;\n");
        __syncthreads();
        const float* s = sbuf[c & 1];
        int l0 = c * ST;
#pragma unroll 4
        for (int ll = 0; ll < ST; ll++) {
            const float* row = s + ll * SROW;
            float dtv = row[ch];
            float uv  = row[8 + ch];
            float bv  = row[16 + n];
            float cv  = row[32 + n];
            float dA = __expf(dtv * a);
            h = fmaf(h, dA, dtv * bv * uv);
            float yp = h * cv;
            yp += __shfl_xor_sync(0xffffffffu, yp, 1);
            yp += __shfl_xor_sync(0xffffffffu, yp, 2);
            yp += __shfl_xor_sync(0xffffffffu, yp, 4);
            yp += __shfl_xor_sync(0xffffffffu, yp, 8);
            if (n == 0) {
                float zv = row[48 + ch];
                float sz = zv / (1.f + __expf(-zv));
                yB[(size_t)(l0 + ll) * CC] = __float2bfloat16((yp + Dv * uv) * sz);
            }
        }
        __syncthreads();   // buffer (c&1) free before iteration c+1 issues chunk c+2 into it
    }
}

// ---------------- host side ----------------
template <typename T> static T* sym(const void* s) {
    void* p = nullptr; cudaGetSymbolAddress(&p, s); return (T*)p;
}

extern "C" void kernel_launch(void* const* d_in, const int* in_sizes, int n_in,
                              void* d_out, int out_size) {
    const float* x       = (const float*)d_in[0];
    const float* norm_w  = (const float*)d_in[1];
    const float* norm_b  = (const float*)d_in[2];
    const float* fus_w1  = (const float*)d_in[21];
    const float* fus_b1  = (const float*)d_in[22];
    const float* fus_w2  = (const float*)d_in[23];
    const float* fus_b2  = (const float*)d_in[24];
    float* out = (float*)d_out;

    const float* in_w [2] = {(const float*)d_in[3],  (const float*)d_in[12]};
    const float* cv_w [2] = {(const float*)d_in[4],  (const float*)d_in[13]};
    const float* cv_b [2] = {(const float*)d_in[5],  (const float*)d_in[14]};
    const float* xp_w [2] = {(const float*)d_in[6],  (const float*)d_in[15]};
    const float* dtp_w[2] = {(const float*)d_in[7],  (const float*)d_in[16]};
    const float* dtp_b[2] = {(const float*)d_in[8],  (const float*)d_in[17]};
    const float* A_log[2] = {(const float*)d_in[9],  (const float*)d_in[18]};
    const float* Dd   [2] = {(const float*)d_in[10], (const float*)d_in[19]};
    const float* out_w[2] = {(const float*)d_in[11], (const float*)d_in[20]};

    __nv_bfloat16* xn16 = sym<__nv_bfloat16>(g_xn16);
    __nv_bfloat16* fused16 = sym<__nv_bfloat16>(g_fused16);
    __nv_bfloat16* h16 = sym<__nv_bfloat16>(g_h16);
    float* xzp   = sym<float>(g_xz);
    float* dblp  = sym<float>(g_dbl);
    float* dtp   = sym<float>(g_dt);
    __nv_bfloat16* uc16p  = sym<__nv_bfloat16>(g_uc16);
    __nv_bfloat16* dbl16p = sym<__nv_bfloat16>(g_dbl16);
    __nv_bfloat16* y16p   = sym<__nv_bfloat16>(g_y16);
    __nv_bfloat16* inwt  = sym<__nv_bfloat16>(g_inwt);
    __nv_bfloat16* xpt   = sym<__nv_bfloat16>(g_xpt);
    __nv_bfloat16* dtpt  = sym<__nv_bfloat16>(g_dtpt);
    __nv_bfloat16* outwt = sym<__nv_bfloat16>(g_outwt);
    __nv_bfloat16* fw1t  = sym<__nv_bfloat16>(g_fw1t);
    __nv_bfloat16* fw2t  = sym<__nv_bfloat16>(g_fw2t);
    int* idx_cw  = sym<int>(g_idx_cw);
    int* idx_ccw = sym<int>(g_idx_ccw);
    const int* idx[2] = {idx_cw, idx_ccw};

    spiral_idx_kernel<<<1, LL>>>(idx_cw, idx_ccw);

    WAll wa;
    wa.w[0] = {in_w[0],  inwt,                 CC, 2*CC};
    wa.w[1] = {in_w[1],  inwt + 2*CC*CC,       CC, 2*CC};
    wa.w[2] = {xp_w[0],  xpt,                  CC, DBLC};
    wa.w[3] = {xp_w[1],  xpt + DBLC*CC,        CC, DBLC};
    wa.w[4] = {dtp_w[0], dtpt,                 DR, CC};
    wa.w[5] = {dtp_w[1], dtpt + CC*DR,         DR, CC};
    wa.w[6] = {out_w[0], outwt,                CC, CC};
    wa.w[7] = {out_w[1], outwt + CC*CC,        CC, CC};
    wa.w[8] = {fus_w1,   fw1t,                 2*CC, CC};
    wa.w[9] = {fus_w2,   fw2t,                 CC, CC};
    wt_kernel<<<dim3(48, 48, 10), dim3(32, 8)>>>(wa);

    layernorm_kernel<<<MTOT, 256>>>(x, norm_w, norm_b);

    BrArgs a0, a1;
    // in_proj: xn16 @ inwt -> xz (fp32), spiral gather
    a0 = {xn16, inwt,           nullptr, xzp,              nullptr, idx[0], nullptr, 0};
    a1 = {xn16, inwt + 2*CC*CC, nullptr, xzp + MTOT*2*CC,  nullptr, idx[1], nullptr, 0};
    bf16gemm_kernel<<<dim3(12, 32, 2), 256>>>(a0, a1, CC, 2*CC, 2*CC, CC, 0, nullptr);

    conv_silu_kernel<<<dim3((MTOT*CC + 255)/256, 2), 256>>>(cv_w[0], cv_b[0], cv_w[1], cv_b[1]);

    // xproj: uc16 @ xpt -> dbl (fp32 + bf16)
    a0 = {uc16p,           xpt,           nullptr, dblp,             dbl16p,             nullptr, nullptr, 0};
    a1 = {uc16p + MTOT*CC, xpt + DBLC*CC, nullptr, dblp + MTOT*DBLC, dbl16p + MTOT*DBLC, nullptr, nullptr, 0};
    bf16gemm_kernel<<<dim3(1, 32, 2), 256>>>(a0, a1, CC, DBLC, DBLC, CC, 0, nullptr);

    // dt proj + softplus: dbl16[:, :48] @ dtpt -> dt (fp32)
    a0 = {dbl16p,             dtpt,         dtp_b[0], dtp,           nullptr, nullptr, nullptr, 0};
    a1 = {dbl16p + MTOT*DBLC, dtpt + CC*DR, dtp_b[1], dtp + MTOT*CC, nullptr, nullptr, nullptr, 0};
    bf16gemm_kernel<<<dim3(6, 32, 2), 256>>>(a0, a1, DBLC, CC, CC, DR, 2, nullptr);

    // selective scan (smem-staged)
    scan_kernel<<<dim3(BB * (CC / 8), 2), 128>>>(A_log[0], Dd[0], A_log[1], Dd[1]);

    // out proj with spiral scatter into fused16 concat buffer
    a0 = {y16p,           outwt,         nullptr, nullptr, fused16, nullptr, idx[0], 0};
    a1 = {y16p + MTOT*CC, outwt + CC*CC, nullptr, nullptr, fused16, nullptr, idx[1], CC};
    bf16gemm_kernel<<<dim3(6, 32, 2), 256>>>(a0, a1, CC, 2*CC, CC, CC, 0, nullptr);

    // fus1: fused16 @ fw1t + b1, GELU -> h16
    a0 = {fused16, fw1t, fus_b1, nullptr, h16, nullptr, nullptr, 0};
    bf16gemm_kernel<<<dim3(6, 32, 1), 256>>>(a0, a0, 2*CC, CC, CC, 2*CC, 1, nullptr);

    // fus2: h16 @ fw2t + b2 + residual x -> out (fp32)
    a0 = {h16, fw2t, fus_b2, out, nullptr, nullptr, nullptr, 0};
    bf16gemm_kernel<<<dim3(6, 32, 1), 256>>>(a0, a0, CC, CC, CC, CC, 0, x);
}

// round 12
// speedup vs baseline: 5.8565x; 1.0251x over previous
#include <cuda_runtime.h>
#include <cuda_bf16.h>
#include <cstdint>

// Problem constants (fixed by the dataset)
#define BB 4
#define LL 1024
#define HH 32
#define WW 32
#define CC 768
#define NN 16
#define DR 48
#define KK 4
#define MTOT (BB*LL)          // 4096
#define DBLC (DR + 2*NN)      // 80

// ---------------- scratch (no allocations allowed) ----------------
__device__ __nv_bfloat16 g_xn16[MTOT*CC];
__device__ float         g_xz  [2][MTOT*2*CC];
__device__ float         g_uc  [2][MTOT*CC];
__device__ __nv_bfloat16 g_uc16[2][MTOT*CC];
__device__ float         g_dbl [2][MTOT*DBLC];
__device__ __nv_bfloat16 g_dbl16[2][MTOT*DBLC];
__device__ float         g_dt  [2][MTOT*CC];
__device__ __nv_bfloat16 g_y16 [2][MTOT*CC];
__device__ __nv_bfloat16 g_fused16[MTOT*2*CC];
__device__ __nv_bfloat16 g_h16 [MTOT*CC];
__device__ int g_idx_cw [LL];
__device__ int g_idx_ccw[LL];
// bf16 transposed weights Wt[n][k]
__device__ __nv_bfloat16 g_inwt [2][2*CC*CC];
__device__ __nv_bfloat16 g_xpt  [2][DBLC*CC];
__device__ __nv_bfloat16 g_dtpt [2][CC*DR];
__device__ __nv_bfloat16 g_outwt[2][CC*CC];
__device__ __nv_bfloat16 g_fw1t [CC*2*CC];
__device__ __nv_bfloat16 g_fw2t [CC*CC];

// ---------------- spiral index generation ----------------
__global__ void spiral_idx_kernel(int* idx_cw, int* idx_ccw) {
    int cell = threadIdx.x;
    int i = cell / WW, j = cell % WW;
    int r = min(min(i, j), min(HH - 1 - i, WW - 1 - j));
    int h = HH - 2 * r, w = WW - 2 * r;
    int prior = HH * WW - h * w;
    int pos;
    if (i == r)                pos = j - r;
    else if (j == WW - 1 - r)  pos = (w - 1) + (i - r);
    else if (i == HH - 1 - r)  pos = (w - 1) + (h - 1) + (WW - 1 - r - j);
    else                       pos = 2*(w - 1) + (h - 1) + (HH - 1 - r - i);
    idx_cw[prior + pos] = cell;
    if (i == r)                pos = (WW - 1 - r) - j;
    else if (j == r)           pos = (w - 1) + (i - r);
    else if (i == HH - 1 - r)  pos = (w - 1) + (h - 1) + (j - r);
    else                       pos = 2*(w - 1) + (h - 1) + (HH - 1 - r - i);
    idx_ccw[prior + pos] = cell;
}

// ---------------- weight transpose+convert: in[K][N] f32 -> out[N][K] bf16 ----------------
struct WDesc { const float* in; __nv_bfloat16* out; int K; int N; };
struct WAll { WDesc w[10]; };
__global__ void wt_kernel(WAll all) {
    WDesc d = all.w[blockIdx.z];
    int n0 = blockIdx.x * 32, k0 = blockIdx.y * 32;
    if (n0 >= d.N || k0 >= d.K) return;
    __shared__ float t[32][33];
    int tx = threadIdx.x, ty = threadIdx.y;          // 32 x 8
#pragma unroll
    for (int i = 0; i < 32; i += 8) {
        int k = k0 + ty + i, n = n0 + tx;
        t[ty + i][tx] = (k < d.K && n < d.N) ? d.in[(size_t)k * d.N + n] : 0.f;
    }
    __syncthreads();
#pragma unroll
    for (int i = 0; i < 32; i += 8) {
        int n = n0 + ty + i, k = k0 + tx;
        if (n < d.N && k < d.K) d.out[(size_t)n * d.K + k] = __float2bfloat16(t[tx][ty + i]);
    }
}

// ---------------- layernorm -> bf16 ----------------
__global__ void layernorm_kernel(const float* __restrict__ x,
                                 const float* __restrict__ w,
                                 const float* __restrict__ b) {
    int row = blockIdx.x;
    const float* xr = x + (size_t)row * CC;
    float s = 0.f, s2 = 0.f;
    for (int c = threadIdx.x; c < CC; c += 256) {
        float v = xr[c];
        s += v; s2 += v * v;
    }
    __shared__ float sh_s[8], sh_s2[8];
    for (int o = 16; o > 0; o >>= 1) {
        s  += __shfl_xor_sync(0xffffffffu, s,  o);
        s2 += __shfl_xor_sync(0xffffffffu, s2, o);
    }
    int warp = threadIdx.x >> 5, lane = threadIdx.x & 31;
    if (lane == 0) { sh_s[warp] = s; sh_s2[warp] = s2; }
    __syncthreads();
    if (warp == 0) {
        s  = (lane < 8) ? sh_s[lane]  : 0.f;
        s2 = (lane < 8) ? sh_s2[lane] : 0.f;
        for (int o = 4; o > 0; o >>= 1) {
            s  += __shfl_xor_sync(0xffffffffu, s,  o);
            s2 += __shfl_xor_sync(0xffffffffu, s2, o);
        }
        if (lane == 0) { sh_s[0] = s; sh_s2[0] = s2; }
    }
    __syncthreads();
    float mu  = sh_s[0] * (1.f / CC);
    float var = sh_s2[0] * (1.f / CC) - mu * mu;
    float inv = rsqrtf(var + 1e-6f);
    for (int c = threadIdx.x; c < CC; c += 256)
        g_xn16[(size_t)row * CC + c] = __float2bfloat16((xr[c] - mu) * inv * w[c] + b[c]);
}

// ---------------- bf16 tensor-core GEMM: 3-stage pipeline, 1 sync/tile, frag batch ------
// BM=BN=128, BK=32, 256 threads, warp grid 2x4, warp tile 64x32, m16n8k16 bf16
#define APk 40                 // smem pitch in bf16 elems (80 B) — ldmatrix conflict-free
#define STGE (128*APk)         // elems per stage per matrix (5120)
#define NSTG 3
#define STGB (2*STGE*2)        // bytes per stage (A then B) = 20480
#define GEMM_SMEM (NSTG*STGB)  // 61440

struct BrArgs {
    const __nv_bfloat16* A;
    const __nv_bfloat16* Wt;       // [n][k]
    const float* bias;
    float* out32;
    __nv_bfloat16* out16;
    const int* a_perm;
    const int* o_perm;
    int o_coloff;
};

__device__ __forceinline__ void cp16(uint32_t dst, const void* src, int sz) {
    asm volatile("cp.async.cg.shared.global [%0], [%1], 16, %2;\n"
                 :: "r"(dst), "l"(src), "r"(sz));
}
__device__ __forceinline__ void ldsm4(uint32_t addr, uint32_t& r0, uint32_t& r1,
                                      uint32_t& r2, uint32_t& r3) {
    asm volatile("ldmatrix.sync.aligned.m8n8.x4.shared.b16 {%0,%1,%2,%3}, [%4];"
                 : "=r"(r0), "=r"(r1), "=r"(r2), "=r"(r3) : "r"(addr));
}

__global__ __launch_bounds__(256, 2)
void bf16gemm_kernel(BrArgs P0, BrArgs P1, int lda, int ldo, int Nn, int Kk,
                     int act, const float* __restrict__ resid) {
    BrArgs P = (blockIdx.z == 0) ? P0 : P1;
    extern __shared__ __nv_bfloat16 smem[];
    int tid = threadIdx.x;
    int row0 = blockIdx.y * 128, col0 = blockIdx.x * 128;
    int warp = tid >> 5, lane = tid & 31;
    int wm = warp >> 2, wn = warp & 3;
    int g = lane >> 2, t4 = lane & 3;

    // ---- loader mapping: each thread owns one row-slot, two 8-elem chunks
    int lrow = tid >> 1;                 // 0..127
    int kc0 = (tid & 1) * 16, kc1 = kc0 + 8;
    int garow = row0 + lrow;
    if (P.a_perm) garow = (garow & ~(LL - 1)) + P.a_perm[garow & (LL - 1)];
    const __nv_bfloat16* abase = P.A + (size_t)garow * lda;
    int gn = col0 + lrow;
    const __nv_bfloat16* bbase = P.Wt + (size_t)(gn < Nn ? gn : 0) * Kk;
    bool bok = (gn < Nn);

    uint32_t sbase = (uint32_t)__cvta_generic_to_shared(smem);
    uint32_t aoff0 = (lrow * APk + kc0) * 2;
    uint32_t aoff1 = (lrow * APk + kc1) * 2;

    // ---- ldmatrix lane offsets (within a stage)
    uint32_t a_off[4], b_off[2];
    {
        int arl = lane & 15, akhi = (lane >> 4) << 3;
#pragma unroll
        for (int mi = 0; mi < 4; mi++)
            a_off[mi] = ((wm * 64 + mi * 16 + arl) * APk + akhi) * 2;
        int bnr = ((lane >> 4) << 3) + (lane & 7);
        int bkhi = ((lane >> 3) & 1) << 3;
#pragma unroll
        for (int np = 0; np < 2; np++)
            b_off[np] = ((wn * 32 + np * 16 + bnr) * APk + bkhi) * 2;
    }

    float acc[4][4][4];
#pragma unroll
    for (int i = 0; i < 4; i++)
#pragma unroll
        for (int j = 0; j < 4; j++)
#pragma unroll
            for (int q = 0; q < 4; q++) acc[i][j][q] = 0.f;

    int ntiles = (Kk + 31) >> 5;

    auto issue = [&](int t) {
        if (t < ntiles) {
            uint32_t sg = sbase + (uint32_t)(t % NSTG) * STGB;
            int k0 = t * 32;
            int s0 = (k0 + kc0 < Kk) ? 16 : 0, s1 = (k0 + kc1 < Kk) ? 16 : 0;
            cp16(sg + aoff0, abase + k0 + kc0, s0);
            cp16(sg + aoff1, abase + k0 + kc1, s1);
            cp16(sg + STGE*2 + aoff0, bbase + k0 + kc0, bok ? s0 : 0);
            cp16(sg + STGE*2 + aoff1, bbase + k0 + kc1, bok ? s1 : 0);
        }
        asm volatile("cp.async.commit_group;\n");
    };

    issue(0); issue(1);

    for (int t = 0; t < ntiles; t++) {
        asm volatile("cp.async.wait_group 1;\n");
        __syncthreads();
        issue(t + 2);     // stage (t+2)%3 == (t-1)%3: consumed at iter t-1, safe after sync
        uint32_t abuf = sbase + (uint32_t)(t % NSTG) * STGB;
        uint32_t bbuf = abuf + STGE*2;
        // batch all fragment loads for both k16-halves, then all MMAs
        uint32_t af[2][4][4], bf[2][4][2];
#pragma unroll
        for (int kh = 0; kh < 2; kh++) {
#pragma unroll
            for (int mi = 0; mi < 4; mi++)
                ldsm4(abuf + kh * 32 + a_off[mi],
                      af[kh][mi][0], af[kh][mi][1], af[kh][mi][2], af[kh][mi][3]);
#pragma unroll
            for (int np = 0; np < 2; np++)
                ldsm4(bbuf + kh * 32 + b_off[np],
                      bf[kh][2*np][0], bf[kh][2*np][1],
                      bf[kh][2*np+1][0], bf[kh][2*np+1][1]);
        }
#pragma unroll
        for (int kh = 0; kh < 2; kh++)
#pragma unroll
            for (int mi = 0; mi < 4; mi++)
#pragma unroll
                for (int ni = 0; ni < 4; ni++)
                    asm volatile(
                        "mma.sync.aligned.m16n8k16.row.col.f32.bf16.bf16.f32 "
                        "{%0,%1,%2,%3}, {%4,%5,%6,%7}, {%8,%9}, {%0,%1,%2,%3};\n"
                        : "+f"(acc[kh? mi:mi][ni][0]), "+f"(acc[mi][ni][1]),
                          "+f"(acc[mi][ni][2]), "+f"(acc[mi][ni][3])
                        : "r"(af[kh][mi][0]), "r"(af[kh][mi][1]),
                          "r"(af[kh][mi][2]), "r"(af[kh][mi][3]),
                          "r"(bf[kh][ni][0]), "r"(bf[kh][ni][1]));
    }

    // ---- epilogue
#pragma unroll
    for (int mi = 0; mi < 4; mi++) {
#pragma unroll
        for (int half = 0; half < 2; half++) {
            int grow = row0 + wm * 64 + mi * 16 + g + half * 8;
            int orow = grow;
            if (P.o_perm) orow = (grow & ~(LL - 1)) + P.o_perm[grow & (LL - 1)];
#pragma unroll
            for (int ni = 0; ni < 4; ni++) {
                int gc = col0 + wn * 32 + ni * 8 + 2 * t4;
                if (gc >= Nn) continue;
                float v0 = acc[mi][ni][half * 2 + 0];
                float v1 = acc[mi][ni][half * 2 + 1];
                if (P.bias) { v0 += P.bias[gc]; v1 += P.bias[gc + 1]; }
                if (act == 1) {                       // exact GELU
                    v0 = 0.5f * v0 * (1.f + erff(v0 * 0.70710678118654752f));
                    v1 = 0.5f * v1 * (1.f + erff(v1 * 0.70710678118654752f));
                } else if (act == 2) {                // softplus
                    v0 = (v0 > 20.f) ? v0 : log1pf(expf(v0));
                    v1 = (v1 > 20.f) ? v1 : log1pf(expf(v1));
                }
                if (resid) {
                    v0 += resid[(size_t)grow * Nn + gc];
                    v1 += resid[(size_t)grow * Nn + gc + 1];
                }
                size_t oidx = (size_t)orow * ldo + P.o_coloff + gc;
                if (P.out32) *(float2*)(P.out32 + oidx) = make_float2(v0, v1);
                if (P.out16) *(__nv_bfloat162*)(P.out16 + oidx) = __floats2bfloat162_rn(v0, v1);
            }
        }
    }
}

// ---------------- causal depthwise conv (K=4) + SiLU, dual-branch ----------------
__global__ void conv_silu_kernel(const float* __restrict__ cw0, const float* __restrict__ cb0,
                                 const float* __restrict__ cw1, const float* __restrict__ cb1) {
    int br = blockIdx.y;
    const float* xz = g_xz[br];
    const float* cw = br ? cw1 : cw0;
    const float* cb = br ? cb1 : cb0;
    int t = blockIdx.x * blockDim.x + threadIdx.x;
    if (t >= MTOT * CC) return;
    int d = t % CC;
    int m = t / CC;
    int l = m & (LL - 1);
    float acc = cb[d];
#pragma unroll
    for (int k = 0; k < KK; k++) {
        int ls = l - (KK - 1) + k;
        if (ls >= 0) acc = fmaf(cw[d * KK + k],
                                xz[(size_t)(m - (KK - 1) + k) * (2 * CC) + d], acc);
    }
    float s = 1.f / (1.f + __expf(-acc));
    float v = acc * s;
    g_uc[br][t] = v;
    g_uc16[br][t] = __float2bfloat16(v);
}

// ---------------- selective scan: smem-staged cp.async pipeline ----------------
#define ST 64
#define SROW 56
__global__ __launch_bounds__(128)
void scan_kernel(const float* __restrict__ A0, const float* __restrict__ D0,
                 const float* __restrict__ A1, const float* __restrict__ D1) {
    int br = blockIdx.y;
    int b  = blockIdx.x / (CC / 8);
    int d0 = (blockIdx.x % (CC / 8)) * 8;
    const float* __restrict__ dt  = g_dt[br];
    const float* __restrict__ dbl = g_dbl[br];
    const float* __restrict__ uc  = g_uc[br];
    const float* __restrict__ xz  = g_xz[br];
    const float* Alog = br ? A1 : A0;
    const float* Dp   = br ? D1 : D0;
    int tid = threadIdx.x;
    int ch = tid >> 4;            // 0..7
    int n  = tid & 15;
    int d  = d0 + ch;
    float a  = -expf(Alog[d * NN + n]);
    float Dv = Dp[d];
    size_t mbase = (size_t)b * LL;

    __shared__ float sbuf[2][ST * SROW];
    uint32_t sb = (uint32_t)__cvta_generic_to_shared(sbuf);

    const float* dtB = dt  + mbase * CC + d0;
    const float* ucB = uc  + mbase * CC + d0;
    const float* bcB = dbl + mbase * DBLC + DR;
    const float* zB  = xz  + mbase * 2 * CC + CC + d0;
    __nv_bfloat16* yB = g_y16[br] + mbase * CC + d;

    auto issue = [&](int c) {
        int l0 = c * ST;
        uint32_t dstb = sb + (uint32_t)(c & 1) * (ST * SROW * 4);
        for (int j = tid; j < ST * 14; j += 128) {
            int ll = j / 14, piece = j % 14;
            int l = l0 + ll;
            uint32_t dst = dstb + (uint32_t)(ll * SROW + piece * 4) * 4;
            const float* src;
            if (piece < 2)       src = dtB + (size_t)l * CC   + piece * 4;
            else if (piece < 4)  src = ucB + (size_t)l * CC   + (piece - 2) * 4;
            else if (piece < 12) src = bcB + (size_t)l * DBLC + (piece - 4) * 4;
            else                 src = zB  + (size_t)l * 2*CC + (piece - 12) * 4;
            cp16(dst, src, 16);
        }
        asm volatile("cp.async.commit_group;\n");
    };

    issue(0);
    float h = 0.f;
    const int NCH = LL / ST;      // 16
    for (int c = 0; c < NCH; c++) {
        if (c + 1 < NCH) issue(c + 1);
        else asm volatile("cp.async.commit_group;\n");
        asm volatile("cp.async.wait_group 1;\n");
        __syncthreads();
        const float* s = sbuf[c & 1];
        int l0 = c * ST;
#pragma unroll 4
        for (int ll = 0; ll < ST; ll++) {
            const float* row = s + ll * SROW;
            float dtv = row[ch];
            float uv  = row[8 + ch];
            float bv  = row[16 + n];
            float cv  = row[32 + n];
            float dA = __expf(dtv * a);
            h = fmaf(h, dA, dtv * bv * uv);
            float yp = h * cv;
            yp += __shfl_xor_sync(0xffffffffu, yp, 1);
            yp += __shfl_xor_sync(0xffffffffu, yp, 2);
            yp += __shfl_xor_sync(0xffffffffu, yp, 4);
            yp += __shfl_xor_sync(0xffffffffu, yp, 8);
            if (n == 0) {
                float zv = row[48 + ch];
                float sz = zv / (1.f + __expf(-zv));
                yB[(size_t)(l0 + ll) * CC] = __float2bfloat16((yp + Dv * uv) * sz);
            }
        }
        __syncthreads();
    }
}

// ---------------- host side ----------------
template <typename T> static T* sym(const void* s) {
    void* p = nullptr; cudaGetSymbolAddress(&p, s); return (T*)p;
}

extern "C" void kernel_launch(void* const* d_in, const int* in_sizes, int n_in,
                              void* d_out, int out_size) {
    const float* x       = (const float*)d_in[0];
    const float* norm_w  = (const float*)d_in[1];
    const float* norm_b  = (const float*)d_in[2];
    const float* fus_w1  = (const float*)d_in[21];
    const float* fus_b1  = (const float*)d_in[22];
    const float* fus_w2  = (const float*)d_in[23];
    const float* fus_b2  = (const float*)d_in[24];
    float* out = (float*)d_out;

    const float* in_w [2] = {(const float*)d_in[3],  (const float*)d_in[12]};
    const float* cv_w [2] = {(const float*)d_in[4],  (const float*)d_in[13]};
    const float* cv_b [2] = {(const float*)d_in[5],  (const float*)d_in[14]};
    const float* xp_w [2] = {(const float*)d_in[6],  (const float*)d_in[15]};
    const float* dtp_w[2] = {(const float*)d_in[7],  (const float*)d_in[16]};
    const float* dtp_b[2] = {(const float*)d_in[8],  (const float*)d_in[17]};
    const float* A_log[2] = {(const float*)d_in[9],  (const float*)d_in[18]};
    const float* Dd   [2] = {(const float*)d_in[10], (const float*)d_in[19]};
    const float* out_w[2] = {(const float*)d_in[11], (const float*)d_in[20]};

    __nv_bfloat16* xn16 = sym<__nv_bfloat16>(g_xn16);
    __nv_bfloat16* fused16 = sym<__nv_bfloat16>(g_fused16);
    __nv_bfloat16* h16 = sym<__nv_bfloat16>(g_h16);
    float* xzp   = sym<float>(g_xz);
    float* dblp  = sym<float>(g_dbl);
    float* dtp   = sym<float>(g_dt);
    __nv_bfloat16* uc16p  = sym<__nv_bfloat16>(g_uc16);
    __nv_bfloat16* dbl16p = sym<__nv_bfloat16>(g_dbl16);
    __nv_bfloat16* y16p   = sym<__nv_bfloat16>(g_y16);
    __nv_bfloat16* inwt  = sym<__nv_bfloat16>(g_inwt);
    __nv_bfloat16* xpt   = sym<__nv_bfloat16>(g_xpt);
    __nv_bfloat16* dtpt  = sym<__nv_bfloat16>(g_dtpt);
    __nv_bfloat16* outwt = sym<__nv_bfloat16>(g_outwt);
    __nv_bfloat16* fw1t  = sym<__nv_bfloat16>(g_fw1t);
    __nv_bfloat16* fw2t  = sym<__nv_bfloat16>(g_fw2t);
    int* idx_cw  = sym<int>(g_idx_cw);
    int* idx_ccw = sym<int>(g_idx_ccw);
    const int* idx[2] = {idx_cw, idx_ccw};

    cudaFuncSetAttribute(bf16gemm_kernel,
                         cudaFuncAttributeMaxDynamicSharedMemorySize, GEMM_SMEM);

    spiral_idx_kernel<<<1, LL>>>(idx_cw, idx_ccw);

    WAll wa;
    wa.w[0] = {in_w[0],  inwt,                 CC, 2*CC};
    wa.w[1] = {in_w[1],  inwt + 2*CC*CC,       CC, 2*CC};
    wa.w[2] = {xp_w[0],  xpt,                  CC, DBLC};
    wa.w[3] = {xp_w[1],  xpt + DBLC*CC,        CC, DBLC};
    wa.w[4] = {dtp_w[0], dtpt,                 DR, CC};
    wa.w[5] = {dtp_w[1], dtpt + CC*DR,         DR, CC};
    wa.w[6] = {out_w[0], outwt,                CC, CC};
    wa.w[7] = {out_w[1], outwt + CC*CC,        CC, CC};
    wa.w[8] = {fus_w1,   fw1t,                 2*CC, CC};
    wa.w[9] = {fus_w2,   fw2t,                 CC, CC};
    wt_kernel<<<dim3(48, 48, 10), dim3(32, 8)>>>(wa);

    layernorm_kernel<<<MTOT, 256>>>(x, norm_w, norm_b);

    BrArgs a0, a1;
    // in_proj: xn16 @ inwt -> xz (fp32), spiral gather
    a0 = {xn16, inwt,           nullptr, xzp,              nullptr, idx[0], nullptr, 0};
    a1 = {xn16, inwt + 2*CC*CC, nullptr, xzp + MTOT*2*CC,  nullptr, idx[1], nullptr, 0};
    bf16gemm_kernel<<<dim3(12, 32, 2), 256, GEMM_SMEM>>>(a0, a1, CC, 2*CC, 2*CC, CC, 0, nullptr);

    conv_silu_kernel<<<dim3((MTOT*CC + 255)/256, 2), 256>>>(cv_w[0], cv_b[0], cv_w[1], cv_b[1]);

    // xproj: uc16 @ xpt -> dbl (fp32 + bf16)
    a0 = {uc16p,           xpt,           nullptr, dblp,             dbl16p,             nullptr, nullptr, 0};
    a1 = {uc16p + MTOT*CC, xpt + DBLC*CC, nullptr, dblp + MTOT*DBLC, dbl16p + MTOT*DBLC, nullptr, nullptr, 0};
    bf16gemm_kernel<<<dim3(1, 32, 2), 256, GEMM_SMEM>>>(a0, a1, CC, DBLC, DBLC, CC, 0, nullptr);

    // dt proj + softplus: dbl16[:, :48] @ dtpt -> dt (fp32)
    a0 = {dbl16p,             dtpt,         dtp_b[0], dtp,           nullptr, nullptr, nullptr, 0};
    a1 = {dbl16p + MTOT*DBLC, dtpt + CC*DR, dtp_b[1], dtp + MTOT*CC, nullptr, nullptr, nullptr, 0};
    bf16gemm_kernel<<<dim3(6, 32, 2), 256, GEMM_SMEM>>>(a0, a1, DBLC, CC, CC, DR, 2, nullptr);

    // selective scan (smem-staged)
    scan_kernel<<<dim3(BB * (CC / 8), 2), 128>>>(A_log[0], Dd[0], A_log[1], Dd[1]);

    // out proj with spiral scatter into fused16 concat buffer
    a0 = {y16p,           outwt,         nullptr, nullptr, fused16, nullptr, idx[0], 0};
    a1 = {y16p + MTOT*CC, outwt + CC*CC, nullptr, nullptr, fused16, nullptr, idx[1], CC};
    bf16gemm_kernel<<<dim3(6, 32, 2), 256, GEMM_SMEM>>>(a0, a1, CC, 2*CC, CC, CC, 0, nullptr);

    // fus1: fused16 @ fw1t + b1, GELU -> h16
    a0 = {fused16, fw1t, fus_b1, nullptr, h16, nullptr, nullptr, 0};
    bf16gemm_kernel<<<dim3(6, 32, 1), 256, GEMM_SMEM>>>(a0, a0, 2*CC, CC, CC, 2*CC, 1, nullptr);

    // fus2: h16 @ fw2t + b2 + residual x -> out (fp32)
    a0 = {h16, fw2t, fus_b2, out, nullptr, nullptr, nullptr, 0};
    bf16gemm_kernel<<<dim3(6, 32, 1), 256, GEMM_SMEM>>>(a0, a0, CC, CC, CC, CC, 0, x);
}